// round 10
// baseline (speedup 1.0000x reference)
#include <cuda_runtime.h>
#include <cuda_bf16.h>
#include <math.h>
#include <stdint.h>

#define Bb 16
#define Dd 384
#define Nn_ 8192
#define Hh 512
#define SCALE 0.125f
#define EPSLN 1e-5f
#define NSPLIT 16

// ---------------- static scratch ----------------
__device__ __nv_bfloat16 g_xn[(long)Bb * Dd * Nn_];     // LN(x), bf16, [b][d][n]
__device__ __nv_bfloat16 g_kv[(long)Bb * 1024 * Nn_];   // rows 0..511 exp(k), 512..1023 v
__device__ float         g_ctxpart[(long)NSPLIT * 128 * 4096];
__device__ float         g_rowsum[Bb * 512];
__device__ __nv_bfloat16 g_T[(long)Bb * 384 * 512];
__device__ __nv_bfloat16 g_wf[(long)Bb * 384 * 384];
__device__ __nv_bfloat16 g_wqkv_bf[1536 * 384];

// ---------------- mma.sync helpers ----------------
__device__ __forceinline__ void ldsm_x4(unsigned addr, unsigned &r0, unsigned &r1,
                                        unsigned &r2, unsigned &r3) {
    asm volatile("ldmatrix.sync.aligned.m8n8.x4.shared.b16 {%0,%1,%2,%3}, [%4];\n"
                 : "=r"(r0), "=r"(r1), "=r"(r2), "=r"(r3) : "r"(addr));
}
__device__ __forceinline__ void ldsm_x4_t(unsigned addr, unsigned &r0, unsigned &r1,
                                          unsigned &r2, unsigned &r3) {
    asm volatile("ldmatrix.sync.aligned.m8n8.x4.trans.shared.b16 {%0,%1,%2,%3}, [%4];\n"
                 : "=r"(r0), "=r"(r1), "=r"(r2), "=r"(r3) : "r"(addr));
}
__device__ __forceinline__ void mma16816(float *c, const unsigned *a, unsigned b0, unsigned b1) {
    asm volatile("mma.sync.aligned.m16n8k16.row.col.f32.bf16.bf16.f32 "
                 "{%0,%1,%2,%3}, {%4,%5,%6,%7}, {%8,%9}, {%0,%1,%2,%3};\n"
                 : "+f"(c[0]), "+f"(c[1]), "+f"(c[2]), "+f"(c[3])
                 : "r"(a[0]), "r"(a[1]), "r"(a[2]), "r"(a[3]), "r"(b0), "r"(b1));
}
__device__ __forceinline__ void cpa16(uint32_t s, const void* g) {
    asm volatile("cp.async.cg.shared.global [%0], [%1], 16;" :: "r"(s), "l"(g));
}
__device__ __forceinline__ void cpa_commit() { asm volatile("cp.async.commit_group;" ::: "memory"); }
template<int NN>
__device__ __forceinline__ void cpa_wait() { asm volatile("cp.async.wait_group %0;" :: "n"(NN) : "memory"); }

// ================= BK=64 GEMM, 4 warps of 64x64, 3-stage cp.async =========
// EPI 0: bf16 out; rows<512 exp() + rowsum atomics  (fused kv-GEMM)
// EPI 1: fp32 out + bias[row] + resid               (GEMM7)
#define ASTR64 72
#define B64STR 136
#define A64_SZ (128 * ASTR64)           // halves per stage
#define B64_SZ (64 * B64STR)
#define G64_SMEM (3 * (A64_SZ + B64_SZ) * 2)   // 107520 B

template<int EPI>
__global__ __launch_bounds__(128, 2)
void gemm_b64(const __nv_bfloat16* __restrict__ A, const __nv_bfloat16* __restrict__ B,
              void* __restrict__ Cv, int K, int N,
              long sA, long sB, long sC,
              const float* __restrict__ bias, const float* __restrict__ resid, long sRes,
              float* __restrict__ rowsum) {
    extern __shared__ __nv_bfloat16 smem[];
    __nv_bfloat16* As = smem;
    __nv_bfloat16* Bs = smem + 3 * A64_SZ;

    int tid = threadIdx.x, lane = tid & 31, wid = tid >> 5;
    int bz = blockIdx.z;
    const __nv_bfloat16* Ab = A + (long)bz * sA;
    const __nv_bfloat16* Bp = B + (long)bz * sB;
    int bm0 = blockIdx.x * 128, bn0 = blockIdx.y * 128;

    uint32_t as_base = (uint32_t)__cvta_generic_to_shared(As);
    uint32_t bs_base = (uint32_t)__cvta_generic_to_shared(Bs);

    int nch = K / 64;
    auto load_stage = [&](int c, int buf) {
        int k0 = c * 64;
        #pragma unroll
        for (int i = 0; i < 8; i++) {          // A: 128 rows x 64 halves
            int v = i * 128 + tid;
            int row = v >> 3, kq = v & 7;
            cpa16(as_base + (uint32_t)(buf * A64_SZ + row * ASTR64 + kq * 8) * 2,
                  Ab + (long)(bm0 + row) * K + k0 + kq * 8);
        }
        #pragma unroll
        for (int i = 0; i < 8; i++) {          // B: 64 rows x 128 halves
            int v = i * 128 + tid;
            int row = v >> 4, q = v & 15;
            cpa16(bs_base + (uint32_t)(buf * B64_SZ + row * B64STR + q * 8) * 2,
                  Bp + (long)(k0 + row) * N + bn0 + q * 8);
        }
        cpa_commit();
    };

    // warp tile 64x64
    int gid = lane >> 2, tid4 = lane & 3;
    int rsel = lane & 15, csel = (lane >> 4) * 8;
    int wm = (wid & 1) * 64, wn = (wid >> 1) * 64;

    float acc[4][8][4];
    #pragma unroll
    for (int i = 0; i < 4; i++)
        #pragma unroll
        for (int j = 0; j < 8; j++)
            #pragma unroll
            for (int k = 0; k < 4; k++) acc[i][j][k] = 0.f;

    load_stage(0, 0); load_stage(1, 1);

    #pragma unroll 1
    for (int c = 0; c < nch; c++) {
        int buf = c % 3;
        cpa_wait<1>();
        __syncthreads();
        if (c + 2 < nch) load_stage(c + 2, (c + 2) % 3);
        #pragma unroll
        for (int ks = 0; ks < 64; ks += 16) {
            unsigned a[4][4], bf[4][4];
            #pragma unroll
            for (int mt = 0; mt < 4; mt++) {
                unsigned addr = as_base +
                    (uint32_t)(buf * A64_SZ + (wm + mt * 16 + rsel) * ASTR64 + ks + csel) * 2;
                ldsm_x4(addr, a[mt][0], a[mt][1], a[mt][2], a[mt][3]);
            }
            #pragma unroll
            for (int nt2 = 0; nt2 < 4; nt2++) {
                unsigned addr = bs_base +
                    (uint32_t)(buf * B64_SZ + (ks + rsel) * B64STR + wn + nt2 * 16 + csel) * 2;
                ldsm_x4_t(addr, bf[nt2][0], bf[nt2][1], bf[nt2][2], bf[nt2][3]);
            }
            #pragma unroll
            for (int mt = 0; mt < 4; mt++)
                #pragma unroll
                for (int nt = 0; nt < 8; nt++)
                    mma16816(acc[mt][nt], a[mt], bf[nt >> 1][(nt & 1) * 2],
                             bf[nt >> 1][(nt & 1) * 2 + 1]);
        }
        __syncthreads();
    }

    if (EPI == 0) {
        __nv_bfloat16* Cb = (__nv_bfloat16*)Cv + (long)bz * sC;
        bool isk = (bm0 < 512);
        float rs[8];
        #pragma unroll
        for (int i = 0; i < 8; i++) rs[i] = 0.f;
        #pragma unroll
        for (int mt = 0; mt < 4; mt++) {
            int row = bm0 + wm + mt * 16 + gid;
            #pragma unroll
            for (int nt = 0; nt < 8; nt++) {
                int col = bn0 + wn + nt * 8 + 2 * tid4;
                float c0 = acc[mt][nt][0], c1 = acc[mt][nt][1];
                float c2 = acc[mt][nt][2], c3 = acc[mt][nt][3];
                if (isk) {
                    c0 = __expf(c0); c1 = __expf(c1);
                    c2 = __expf(c2); c3 = __expf(c3);
                    rs[mt * 2] += c0 + c1;
                    rs[mt * 2 + 1] += c2 + c3;
                }
                *(__nv_bfloat162*)&Cb[(long)row * N + col] = __floats2bfloat162_rn(c0, c1);
                *(__nv_bfloat162*)&Cb[(long)(row + 8) * N + col] = __floats2bfloat162_rn(c2, c3);
            }
        }
        if (isk) {
            #pragma unroll
            for (int i = 0; i < 8; i++) {
                rs[i] += __shfl_xor_sync(0xffffffffu, rs[i], 1);
                rs[i] += __shfl_xor_sync(0xffffffffu, rs[i], 2);
            }
            if (tid4 == 0) {
                #pragma unroll
                for (int mt = 0; mt < 4; mt++) {
                    int row = bm0 + wm + mt * 16 + gid;
                    atomicAdd(&rowsum[bz * 512 + row], rs[mt * 2]);
                    atomicAdd(&rowsum[bz * 512 + row + 8], rs[mt * 2 + 1]);
                }
            }
        }
    } else {
        float* Cf = (float*)Cv + (long)bz * sC;
        const float* rp = resid + (long)bz * sRes;
        #pragma unroll
        for (int mt = 0; mt < 4; mt++) {
            int row = bm0 + wm + mt * 16 + gid;
            float b1 = bias[row], b2 = bias[row + 8];
            #pragma unroll
            for (int nt = 0; nt < 8; nt++) {
                int col = bn0 + wn + nt * 8 + 2 * tid4;
                float2 r1 = *(const float2*)&rp[(long)row * N + col];
                float2 r2 = *(const float2*)&rp[(long)(row + 8) * N + col];
                float2 o1 = make_float2(acc[mt][nt][0] + b1 + r1.x, acc[mt][nt][1] + b1 + r1.y);
                float2 o2 = make_float2(acc[mt][nt][2] + b2 + r2.x, acc[mt][nt][3] + b2 + r2.y);
                *(float2*)&Cf[(long)row * N + col] = o1;
                *(float2*)&Cf[(long)(row + 8) * N + col] = o2;
            }
        }
    }
}

// ================= R4 128x128 8-warp GEMM (GEMM6 only) =================
#define ASTRIDE 40
#define BSTRIDE 136
#define A_ST_SZ (128 * ASTRIDE)
#define B_ST_SZ (32 * BSTRIDE)
#define GSMEM_BYTES ((4 * A_ST_SZ + 4 * B_ST_SZ) * 2)

__global__ __launch_bounds__(256)
void gemm_small(const __nv_bfloat16* __restrict__ A, const __nv_bfloat16* __restrict__ B,
                __nv_bfloat16* __restrict__ C, int K, int N,
                long sA, long sB, long sC, float scale) {
    extern __shared__ __nv_bfloat16 smem[];
    __nv_bfloat16* As = smem;
    __nv_bfloat16* Bs = smem + 4 * A_ST_SZ;
    int tid = threadIdx.x, lane = tid & 31, wid = tid >> 5;
    int bz = blockIdx.z;
    const __nv_bfloat16* Ab = A + (long)bz * sA;
    const __nv_bfloat16* Bp = B + (long)bz * sB;
    int bm0 = blockIdx.x * 128, bn0 = blockIdx.y * 128;
    int am = tid >> 2, akq = tid & 3;
    int bk = tid >> 4, bnq = tid & 15;
    const __nv_bfloat16* Ag0 = Ab + (long)(bm0 + am) * K + akq * 8;
    const __nv_bfloat16* Ag1 = Ag0 + (long)64 * K;
    const __nv_bfloat16* Bg0 = Bp + (long)bk * N + bn0 + bnq * 8;
    const __nv_bfloat16* Bg1 = Bg0 + (long)16 * N;
    uint32_t a_s0 = (uint32_t)__cvta_generic_to_shared(&As[am * ASTRIDE + akq * 8]);
    uint32_t a_s1 = (uint32_t)__cvta_generic_to_shared(&As[(am + 64) * ASTRIDE + akq * 8]);
    uint32_t b_s0 = (uint32_t)__cvta_generic_to_shared(&Bs[bk * BSTRIDE + bnq * 8]);
    uint32_t b_s1 = (uint32_t)__cvta_generic_to_shared(&Bs[(bk + 16) * BSTRIDE + bnq * 8]);
    int nch = K / 32;
    auto load_stage = [&](int c, int buf) {
        int k0 = c * 32;
        cpa16(a_s0 + buf * A_ST_SZ * 2, Ag0 + k0);
        cpa16(a_s1 + buf * A_ST_SZ * 2, Ag1 + k0);
        cpa16(b_s0 + buf * B_ST_SZ * 2, Bg0 + (long)k0 * N);
        cpa16(b_s1 + buf * B_ST_SZ * 2, Bg1 + (long)k0 * N);
        cpa_commit();
    };
    int gid = lane >> 2, tid4 = lane & 3;
    int rsel = lane & 15, csel = (lane >> 4) * 8;
    int wm = (wid & 1) * 64, wn = (wid >> 1) * 32;
    uint32_t as_base = (uint32_t)__cvta_generic_to_shared(As);
    uint32_t bs_base = (uint32_t)__cvta_generic_to_shared(Bs);
    float acc[4][4][4];
    #pragma unroll
    for (int i = 0; i < 4; i++)
        #pragma unroll
        for (int j = 0; j < 4; j++)
            #pragma unroll
            for (int k = 0; k < 4; k++) acc[i][j][k] = 0.f;
    load_stage(0, 0); load_stage(1, 1); load_stage(2, 2);
    #pragma unroll 1
    for (int c = 0; c < nch; c++) {
        int buf = c & 3;
        cpa_wait<2>();
        __syncthreads();
        if (c + 3 < nch) load_stage(c + 3, (c + 3) & 3);
        #pragma unroll
        for (int ks = 0; ks < 32; ks += 16) {
            unsigned a[4][4], bf[2][4];
            #pragma unroll
            for (int mt = 0; mt < 4; mt++) {
                unsigned addr = as_base +
                    (buf * A_ST_SZ + (wm + mt * 16 + rsel) * ASTRIDE + ks + csel) * 2;
                ldsm_x4(addr, a[mt][0], a[mt][1], a[mt][2], a[mt][3]);
            }
            #pragma unroll
            for (int nt2 = 0; nt2 < 2; nt2++) {
                unsigned addr = bs_base +
                    (buf * B_ST_SZ + (ks + rsel) * BSTRIDE + wn + nt2 * 16 + csel) * 2;
                ldsm_x4_t(addr, bf[nt2][0], bf[nt2][1], bf[nt2][2], bf[nt2][3]);
            }
            #pragma unroll
            for (int mt = 0; mt < 4; mt++)
                #pragma unroll
                for (int nt = 0; nt < 4; nt++)
                    mma16816(acc[mt][nt], a[mt], bf[nt >> 1][(nt & 1) * 2],
                             bf[nt >> 1][(nt & 1) * 2 + 1]);
        }
        __syncthreads();
    }
    #pragma unroll
    for (int mt = 0; mt < 4; mt++) {
        int row = bm0 + wm + mt * 16 + gid;
        #pragma unroll
        for (int nt = 0; nt < 4; nt++) {
            int col = bn0 + wn + nt * 8 + 2 * tid4;
            __nv_bfloat16* Cb = C + (long)bz * sC;
            *(__nv_bfloat162*)&Cb[(long)row * N + col] =
                __floats2bfloat162_rn(acc[mt][nt][0] * scale, acc[mt][nt][1] * scale);
            *(__nv_bfloat162*)&Cb[(long)(row + 8) * N + col] =
                __floats2bfloat162_rn(acc[mt][nt][2] * scale, acc[mt][nt][3] * scale);
        }
    }
}

// ================= small kernels =================
__global__ void cvt_kernel(const float* __restrict__ src, __nv_bfloat16* __restrict__ dst, int n) {
    int i = blockIdx.x * blockDim.x + threadIdx.x;
    if (i < n) dst[i] = __float2bfloat16(src[i]);
}
__global__ void zero_kernel(float* p, int n) {
    int i = blockIdx.x * blockDim.x + threadIdx.x;
    if (i < n) p[i] = 0.f;
}

__global__ __launch_bounds__(256) void ln_norm_kernel(const float* __restrict__ x,
                                                      const float* __restrict__ gamma,
                                                      const float* __restrict__ beta,
                                                      __nv_bfloat16* __restrict__ xn) {
    __shared__ float gS[384], bS[384];
    __shared__ float red_s[8][33], red_q[8][33];
    __shared__ float mS[32], rS[32];
    int tid = threadIdx.x;
    int dg = tid >> 5, tn = tid & 31;
    int b = blockIdx.y;
    int n = blockIdx.x * 32 + tn;
    for (int i = tid; i < 384; i += 256) { gS[i] = gamma[i]; bS[i] = beta[i]; }
    const float* xp = x + (long)b * Dd * Nn_ + n;
    float v[48];
    float s = 0.f, q = 0.f;
    #pragma unroll
    for (int i = 0; i < 48; i++) {
        int d = dg + i * 8;
        v[i] = xp[(long)d * Nn_];
        s += v[i]; q += v[i] * v[i];
    }
    red_s[dg][tn] = s; red_q[dg][tn] = q;
    __syncthreads();
    if (dg == 0) {
        float ts = 0.f, tq = 0.f;
        #pragma unroll
        for (int j = 0; j < 8; j++) { ts += red_s[j][tn]; tq += red_q[j][tn]; }
        float mean = ts * (1.0f / Dd);
        float var = tq * (1.0f / Dd) - mean * mean;
        mS[tn] = mean; rS[tn] = rsqrtf(var + EPSLN);
    }
    __syncthreads();
    float mean = mS[tn], rstd = rS[tn];
    __nv_bfloat16* xo = xn + (long)b * Dd * Nn_ + n;
    #pragma unroll
    for (int i = 0; i < 48; i++) {
        int d = dg + i * 8;
        xo[(long)d * Nn_] = __float2bfloat16((v[i] - mean) * rstd * gS[d] + bS[d]);
    }
}

// ---------------- context via mma.sync (k already exp'd) ----------------
__global__ __launch_bounds__(256) void context_mma_kernel(const __nv_bfloat16* __restrict__ kv,
                                                          float* __restrict__ ctx_part) {
    __shared__ __align__(16) __nv_bfloat16 Ks[2][64 * 72];
    __shared__ __align__(16) __nv_bfloat16 Vs[2][64 * 72];
    const int LEN = Nn_ / NSPLIT;
    int sp = blockIdx.x, bh = blockIdx.y;
    int b = bh >> 3, h = bh & 7;
    const __nv_bfloat16* kb = kv + ((long)b * 1024 + h * 64) * Nn_;
    const __nv_bfloat16* vb = kv + ((long)b * 1024 + 512 + h * 64) * Nn_;
    int tid = threadIdx.x, lane = tid & 31, wid = tid >> 5;
    int lr = tid >> 3, lc = (tid & 7) * 8;
    int n0 = sp * LEN;
    int gid = lane >> 2, tid4 = lane & 3;
    int rsel = lane & 15, csel = (lane >> 4) * 8;
    int wm = (wid & 1) * 32, wn = (wid >> 1) * 16;
    float acc[2][2][4];
    #pragma unroll
    for (int i = 0; i < 2; i++)
        #pragma unroll
        for (int j = 0; j < 2; j++)
            #pragma unroll
            for (int k = 0; k < 4; k++) acc[i][j][k] = 0.f;
    uint4 k0v, k1v, v0v, v1v;
    const int NCH = LEN / 64;
    int so = lr * 72 + lc;
    k0v = *(const uint4*)(kb + (long)lr * Nn_ + n0 + lc);
    k1v = *(const uint4*)(kb + (long)(lr + 32) * Nn_ + n0 + lc);
    v0v = *(const uint4*)(vb + (long)lr * Nn_ + n0 + lc);
    v1v = *(const uint4*)(vb + (long)(lr + 32) * Nn_ + n0 + lc);
    *(uint4*)&Ks[0][so] = k0v; *(uint4*)&Ks[0][so + 32 * 72] = k1v;
    *(uint4*)&Vs[0][so] = v0v; *(uint4*)&Vs[0][so + 32 * 72] = v1v;
    __syncthreads();
    for (int c = 0; c < NCH; c++) {
        int buf = c & 1;
        if (c + 1 < NCH) {
            int off = n0 + (c + 1) * 64 + lc;
            k0v = *(const uint4*)(kb + (long)lr * Nn_ + off);
            k1v = *(const uint4*)(kb + (long)(lr + 32) * Nn_ + off);
            v0v = *(const uint4*)(vb + (long)lr * Nn_ + off);
            v1v = *(const uint4*)(vb + (long)(lr + 32) * Nn_ + off);
        }
        #pragma unroll
        for (int ks = 0; ks < 64; ks += 16) {
            unsigned a[2][4], bf[4];
            #pragma unroll
            for (int mt = 0; mt < 2; mt++) {
                unsigned addr = (unsigned)__cvta_generic_to_shared(
                    &Ks[buf][(wm + mt * 16 + rsel) * 72 + ks + csel]);
                ldsm_x4(addr, a[mt][0], a[mt][1], a[mt][2], a[mt][3]);
            }
            {
                unsigned addr = (unsigned)__cvta_generic_to_shared(
                    &Vs[buf][(wn + rsel) * 72 + ks + csel]);
                ldsm_x4(addr, bf[0], bf[1], bf[2], bf[3]);
            }
            #pragma unroll
            for (int mt = 0; mt < 2; mt++)
                #pragma unroll
                for (int nt = 0; nt < 2; nt++)
                    mma16816(acc[mt][nt], a[mt], bf[nt], bf[nt + 2]);
        }
        if (c + 1 < NCH) {
            int nb = (c + 1) & 1;
            *(uint4*)&Ks[nb][so] = k0v; *(uint4*)&Ks[nb][so + 32 * 72] = k1v;
            *(uint4*)&Vs[nb][so] = v0v; *(uint4*)&Vs[nb][so + 32 * 72] = v1v;
        }
        __syncthreads();
    }
    float* cp = ctx_part + ((long)sp * 128 + bh) * 4096;
    #pragma unroll
    for (int mt = 0; mt < 2; mt++) {
        int row = wm + mt * 16 + gid;
        #pragma unroll
        for (int nt = 0; nt < 2; nt++) {
            int col = wn + nt * 8 + 2 * tid4;
            *(float2*)&cp[row * 64 + col] = make_float2(acc[mt][nt][0], acc[mt][nt][1]);
            *(float2*)&cp[(row + 8) * 64 + col] = make_float2(acc[mt][nt][2], acc[mt][nt][3]);
        }
    }
}

// ------------- T build -------------
__global__ __launch_bounds__(256) void build_T_kernel(const float* __restrict__ ctx_part,
                                                      const float* __restrict__ rowsum,
                                                      const float* __restrict__ wout,
                                                      __nv_bfloat16* __restrict__ T) {
    int bh = blockIdx.x;
    int b = bh >> 3, h = bh & 7;
    __shared__ float ctxS[64][65];
    __shared__ float wS[64][65];
    int tid = threadIdx.x;
    #pragma unroll
    for (int i = 0; i < 16; i++) {
        int idx = tid + i * 256;
        int d = idx >> 6;
        float s = 0.f;
        #pragma unroll
        for (int sp = 0; sp < NSPLIT; sp++)
            s += ctx_part[((long)sp * 128 + bh) * 4096 + idx];
        ctxS[d][idx & 63] = s / rowsum[b * 512 + h * 64 + d];
    }
    __syncthreads();
    __nv_bfloat16* Tb = T + (long)b * 384 * 512;
    for (int c = 0; c < 6; c++) {
        #pragma unroll
        for (int i = 0; i < 16; i++) {
            int idx = tid + i * 256;
            int dr = idx >> 6, e = idx & 63;
            wS[dr][e] = wout[(long)(c * 64 + dr) * Hh + h * 64 + e];
        }
        __syncthreads();
        #pragma unroll
        for (int i = 0; i < 16; i++) {
            int idx = tid + i * 256;
            int dl = idx >> 6, dd = idx & 63;
            float s = 0.f;
            #pragma unroll
            for (int e = 0; e < 64; e++)
                s += wS[dl][e] * ctxS[dd][e];
            Tb[(long)(c * 64 + dl) * 512 + h * 64 + dd] = __float2bfloat16(s);
        }
        __syncthreads();
    }
}

// -------------------------------------------------------------------------
extern "C" void kernel_launch(void* const* d_in, const int* in_sizes, int n_in,
                              void* d_out, int out_size) {
    (void)in_sizes; (void)n_in; (void)out_size;
    const float* x     = (const float*)d_in[0];
    const float* gam   = (const float*)d_in[1];
    const float* bet   = (const float*)d_in[2];
    const float* w_qkv = (const float*)d_in[3];
    const float* w_out = (const float*)d_in[4];
    const float* b_out = (const float*)d_in[5];
    float* out = (float*)d_out;

    __nv_bfloat16 *p_xn, *p_kv, *p_T, *p_wf, *p_wq;
    float *p_ctxp, *p_rowsum;
    cudaGetSymbolAddress((void**)&p_xn,     g_xn);
    cudaGetSymbolAddress((void**)&p_kv,     g_kv);
    cudaGetSymbolAddress((void**)&p_ctxp,   g_ctxpart);
    cudaGetSymbolAddress((void**)&p_rowsum, g_rowsum);
    cudaGetSymbolAddress((void**)&p_T,      g_T);
    cudaGetSymbolAddress((void**)&p_wf,     g_wf);
    cudaGetSymbolAddress((void**)&p_wq,     g_wqkv_bf);

    cudaFuncSetAttribute(gemm_b64<0>, cudaFuncAttributeMaxDynamicSharedMemorySize, G64_SMEM);
    cudaFuncSetAttribute(gemm_b64<1>, cudaFuncAttributeMaxDynamicSharedMemorySize, G64_SMEM);
    cudaFuncSetAttribute(gemm_small, cudaFuncAttributeMaxDynamicSharedMemorySize, GSMEM_BYTES);

    // 0. prep
    cvt_kernel<<<(1536 * 384 + 255) / 256, 256>>>(w_qkv, p_wq, 1536 * 384);
    zero_kernel<<<(Bb * 512 + 255) / 256, 256>>>(p_rowsum, Bb * 512);

    // 1. LN -> bf16 x_norm
    ln_norm_kernel<<<dim3(Nn_ / 32, Bb), 256>>>(x, gam, bet, p_xn);

    // 2. kv = W_kv @ xn (M=1024, fused); k rows exp'd + rowsum atomics
    gemm_b64<0><<<dim3(8, 64, Bb), 128, G64_SMEM>>>(
        p_wq + (long)512 * Dd, p_xn, p_kv, Dd, Nn_,
        0L, (long)Dd * Nn_, (long)1024 * Nn_,
        nullptr, nullptr, 0L, p_rowsum);

    // 3. partial contexts
    context_mma_kernel<<<dim3(NSPLIT, 128), 256>>>(p_kv, p_ctxp);

    // 4. T
    build_T_kernel<<<128, 256>>>(p_ctxp, p_rowsum, w_out, p_T);

    // 5. W_final[b] = SCALE * T[b] @ W_q
    gemm_small<<<dim3(3, 3, Bb), 256, GSMEM_BYTES>>>(
        p_T, p_wq, p_wf, 512, 384,
        (long)384 * 512, 0L, (long)384 * 384, SCALE);

    // 6. out = W_final[b] @ xn + b_out + x
    gemm_b64<1><<<dim3(3, 64, Bb), 128, G64_SMEM>>>(
        p_wf, p_xn, out, Dd, Nn_,
        (long)384 * 384, (long)Dd * Nn_, (long)Dd * Nn_,
        b_out, x, (long)Dd * Nn_, nullptr);
}

// round 11
// speedup vs baseline: 1.0585x; 1.0585x over previous
#include <cuda_runtime.h>
#include <cuda_bf16.h>
#include <math.h>
#include <stdint.h>

#define Bb 16
#define Dd 384
#define Nn_ 8192
#define Hh 512
#define SCALE 0.125f
#define EPSLN 1e-5f
#define NSPLIT 16

// ---------------- static scratch ----------------
__device__ __nv_bfloat16 g_xn[(long)Bb * Dd * Nn_];     // LN(x), bf16, [b][d][n]
__device__ __nv_bfloat16 g_kv[(long)Bb * 1024 * Nn_];   // rows 0..511 exp(k), 512..1023 v
__device__ float         g_ctxpart[(long)NSPLIT * 128 * 4096];
__device__ float         g_rowsum[Bb * 512];
__device__ __nv_bfloat16 g_T[(long)Bb * 384 * 512];
__device__ __nv_bfloat16 g_wf[(long)Bb * 384 * 384];
__device__ __nv_bfloat16 g_wqkv_bf[1536 * 384];

// ---------------- mma.sync helpers ----------------
__device__ __forceinline__ void ldsm_x4(unsigned addr, unsigned &r0, unsigned &r1,
                                        unsigned &r2, unsigned &r3) {
    asm volatile("ldmatrix.sync.aligned.m8n8.x4.shared.b16 {%0,%1,%2,%3}, [%4];\n"
                 : "=r"(r0), "=r"(r1), "=r"(r2), "=r"(r3) : "r"(addr));
}
__device__ __forceinline__ void ldsm_x4_t(unsigned addr, unsigned &r0, unsigned &r1,
                                          unsigned &r2, unsigned &r3) {
    asm volatile("ldmatrix.sync.aligned.m8n8.x4.trans.shared.b16 {%0,%1,%2,%3}, [%4];\n"
                 : "=r"(r0), "=r"(r1), "=r"(r2), "=r"(r3) : "r"(addr));
}
__device__ __forceinline__ void mma16816(float *c, const unsigned *a, unsigned b0, unsigned b1) {
    asm volatile("mma.sync.aligned.m16n8k16.row.col.f32.bf16.bf16.f32 "
                 "{%0,%1,%2,%3}, {%4,%5,%6,%7}, {%8,%9}, {%0,%1,%2,%3};\n"
                 : "+f"(c[0]), "+f"(c[1]), "+f"(c[2]), "+f"(c[3])
                 : "r"(a[0]), "r"(a[1]), "r"(a[2]), "r"(a[3]), "r"(b0), "r"(b1));
}
__device__ __forceinline__ void cpa16(uint32_t s, const void* g) {
    asm volatile("cp.async.cg.shared.global [%0], [%1], 16;" :: "r"(s), "l"(g));
}
__device__ __forceinline__ void cpa_commit() { asm volatile("cp.async.commit_group;" ::: "memory"); }
template<int NN>
__device__ __forceinline__ void cpa_wait() { asm volatile("cp.async.wait_group %0;" :: "n"(NN) : "memory"); }

#define ASTRIDE 40
#define BSTRIDE 136
#define A_ST_SZ (128 * ASTRIDE)
#define B_ST_SZ (32 * BSTRIDE)
#define GSMEM_BYTES ((4 * A_ST_SZ + 4 * B_ST_SZ) * 2)

// ================= 128x128 GEMM, 4 warps of 64x64, 4-stage cp.async =======
// EPI 0: bf16 out; rows<512 exp() + rowsum atomics  (fused kv-GEMM)
// EPI 1: fp32 out + bias[row] + resid               (GEMM7)
template<int EPI>
__global__ __launch_bounds__(128, 2)
void gemm_w64(const __nv_bfloat16* __restrict__ A, const __nv_bfloat16* __restrict__ B,
              void* __restrict__ Cv, int K, int N,
              long sA, long sB, long sC,
              const float* __restrict__ bias, const float* __restrict__ resid, long sRes,
              float* __restrict__ rowsum) {
    extern __shared__ __nv_bfloat16 smem[];
    __nv_bfloat16* As = smem;
    __nv_bfloat16* Bs = smem + 4 * A_ST_SZ;

    int tid = threadIdx.x, lane = tid & 31, wid = tid >> 5;
    int bz = blockIdx.z;
    const __nv_bfloat16* Ab = A + (long)bz * sA;
    const __nv_bfloat16* Bp = B + (long)bz * sB;
    int bm0 = blockIdx.x * 128, bn0 = blockIdx.y * 128;

    uint32_t as_base = (uint32_t)__cvta_generic_to_shared(As);
    uint32_t bs_base = (uint32_t)__cvta_generic_to_shared(Bs);

    int nch = K / 32;
    auto load_stage = [&](int c, int buf) {
        int k0 = c * 32;
        #pragma unroll
        for (int i = 0; i < 4; i++) {          // A: 128 rows x 32 halves
            int v = i * 128 + tid;
            int row = v >> 2, kq = v & 3;
            cpa16(as_base + (uint32_t)(buf * A_ST_SZ + row * ASTRIDE + kq * 8) * 2,
                  Ab + (long)(bm0 + row) * K + k0 + kq * 8);
        }
        #pragma unroll
        for (int i = 0; i < 4; i++) {          // B: 32 rows x 128 halves
            int v = i * 128 + tid;
            int row = v >> 4, q = v & 15;
            cpa16(bs_base + (uint32_t)(buf * B_ST_SZ + row * BSTRIDE + q * 8) * 2,
                  Bp + (long)(k0 + row) * N + bn0 + q * 8);
        }
        cpa_commit();
    };

    // warp tile 64x64: wm in {0,64}, wn in {0,64}
    int gid = lane >> 2, tid4 = lane & 3;
    int rsel = lane & 15, csel = (lane >> 4) * 8;
    int wm = (wid & 1) * 64, wn = (wid >> 1) * 64;

    float acc[4][8][4];
    #pragma unroll
    for (int i = 0; i < 4; i++)
        #pragma unroll
        for (int j = 0; j < 8; j++)
            #pragma unroll
            for (int k = 0; k < 4; k++) acc[i][j][k] = 0.f;

    load_stage(0, 0); load_stage(1, 1); load_stage(2, 2);

    #pragma unroll 1
    for (int c = 0; c < nch; c++) {
        int buf = c & 3;
        cpa_wait<2>();
        __syncthreads();
        if (c + 3 < nch) load_stage(c + 3, (c + 3) & 3);
        #pragma unroll
        for (int ks = 0; ks < 32; ks += 16) {
            unsigned a[4][4], bf[4][4];
            #pragma unroll
            for (int mt = 0; mt < 4; mt++) {
                unsigned addr = as_base +
                    (uint32_t)(buf * A_ST_SZ + (wm + mt * 16 + rsel) * ASTRIDE + ks + csel) * 2;
                ldsm_x4(addr, a[mt][0], a[mt][1], a[mt][2], a[mt][3]);
            }
            #pragma unroll
            for (int nt2 = 0; nt2 < 4; nt2++) {
                unsigned addr = bs_base +
                    (uint32_t)(buf * B_ST_SZ + (ks + rsel) * BSTRIDE + wn + nt2 * 16 + csel) * 2;
                ldsm_x4_t(addr, bf[nt2][0], bf[nt2][1], bf[nt2][2], bf[nt2][3]);
            }
            #pragma unroll
            for (int mt = 0; mt < 4; mt++)
                #pragma unroll
                for (int nt = 0; nt < 8; nt++)
                    mma16816(acc[mt][nt], a[mt], bf[nt >> 1][(nt & 1) * 2],
                             bf[nt >> 1][(nt & 1) * 2 + 1]);
        }
        __syncthreads();
    }

    if (EPI == 0) {
        __nv_bfloat16* Cb = (__nv_bfloat16*)Cv + (long)bz * sC;
        bool isk = (bm0 < 512);
        float rs[8];
        #pragma unroll
        for (int i = 0; i < 8; i++) rs[i] = 0.f;
        #pragma unroll
        for (int mt = 0; mt < 4; mt++) {
            int row = bm0 + wm + mt * 16 + gid;
            #pragma unroll
            for (int nt = 0; nt < 8; nt++) {
                int col = bn0 + wn + nt * 8 + 2 * tid4;
                float c0 = acc[mt][nt][0], c1 = acc[mt][nt][1];
                float c2 = acc[mt][nt][2], c3 = acc[mt][nt][3];
                if (isk) {
                    c0 = __expf(c0); c1 = __expf(c1);
                    c2 = __expf(c2); c3 = __expf(c3);
                    rs[mt * 2] += c0 + c1;
                    rs[mt * 2 + 1] += c2 + c3;
                }
                *(__nv_bfloat162*)&Cb[(long)row * N + col] = __floats2bfloat162_rn(c0, c1);
                *(__nv_bfloat162*)&Cb[(long)(row + 8) * N + col] = __floats2bfloat162_rn(c2, c3);
            }
        }
        if (isk) {
            #pragma unroll
            for (int i = 0; i < 8; i++) {
                rs[i] += __shfl_xor_sync(0xffffffffu, rs[i], 1);
                rs[i] += __shfl_xor_sync(0xffffffffu, rs[i], 2);
            }
            if (tid4 == 0) {
                #pragma unroll
                for (int mt = 0; mt < 4; mt++) {
                    int row = bm0 + wm + mt * 16 + gid;
                    atomicAdd(&rowsum[bz * 512 + row], rs[mt * 2]);
                    atomicAdd(&rowsum[bz * 512 + row + 8], rs[mt * 2 + 1]);
                }
            }
        }
    } else {
        float* Cf = (float*)Cv + (long)bz * sC;
        const float* rp = resid + (long)bz * sRes;
        #pragma unroll
        for (int mt = 0; mt < 4; mt++) {
            int row = bm0 + wm + mt * 16 + gid;
            float b1 = bias[row], b2 = bias[row + 8];
            #pragma unroll
            for (int nt = 0; nt < 8; nt++) {
                int col = bn0 + wn + nt * 8 + 2 * tid4;
                float2 r1 = *(const float2*)&rp[(long)row * N + col];
                float2 r2 = *(const float2*)&rp[(long)(row + 8) * N + col];
                float2 o1 = make_float2(acc[mt][nt][0] + b1 + r1.x, acc[mt][nt][1] + b1 + r1.y);
                float2 o2 = make_float2(acc[mt][nt][2] + b2 + r2.x, acc[mt][nt][3] + b2 + r2.y);
                *(float2*)&Cf[(long)row * N + col] = o1;
                *(float2*)&Cf[(long)(row + 8) * N + col] = o2;
            }
        }
    }
}

// ================= R4 128x128 8-warp GEMM (GEMM6 only) =================
__global__ __launch_bounds__(256)
void gemm_small(const __nv_bfloat16* __restrict__ A, const __nv_bfloat16* __restrict__ B,
                __nv_bfloat16* __restrict__ C, int K, int N,
                long sA, long sB, long sC, float scale) {
    extern __shared__ __nv_bfloat16 smem[];
    __nv_bfloat16* As = smem;
    __nv_bfloat16* Bs = smem + 4 * A_ST_SZ;
    int tid = threadIdx.x, lane = tid & 31, wid = tid >> 5;
    int bz = blockIdx.z;
    const __nv_bfloat16* Ab = A + (long)bz * sA;
    const __nv_bfloat16* Bp = B + (long)bz * sB;
    int bm0 = blockIdx.x * 128, bn0 = blockIdx.y * 128;
    int am = tid >> 2, akq = tid & 3;
    int bk = tid >> 4, bnq = tid & 15;
    const __nv_bfloat16* Ag0 = Ab + (long)(bm0 + am) * K + akq * 8;
    const __nv_bfloat16* Ag1 = Ag0 + (long)64 * K;
    const __nv_bfloat16* Bg0 = Bp + (long)bk * N + bn0 + bnq * 8;
    const __nv_bfloat16* Bg1 = Bg0 + (long)16 * N;
    uint32_t a_s0 = (uint32_t)__cvta_generic_to_shared(&As[am * ASTRIDE + akq * 8]);
    uint32_t a_s1 = (uint32_t)__cvta_generic_to_shared(&As[(am + 64) * ASTRIDE + akq * 8]);
    uint32_t b_s0 = (uint32_t)__cvta_generic_to_shared(&Bs[bk * BSTRIDE + bnq * 8]);
    uint32_t b_s1 = (uint32_t)__cvta_generic_to_shared(&Bs[(bk + 16) * BSTRIDE + bnq * 8]);
    int nch = K / 32;
    auto load_stage = [&](int c, int buf) {
        int k0 = c * 32;
        cpa16(a_s0 + buf * A_ST_SZ * 2, Ag0 + k0);
        cpa16(a_s1 + buf * A_ST_SZ * 2, Ag1 + k0);
        cpa16(b_s0 + buf * B_ST_SZ * 2, Bg0 + (long)k0 * N);
        cpa16(b_s1 + buf * B_ST_SZ * 2, Bg1 + (long)k0 * N);
        cpa_commit();
    };
    int gid = lane >> 2, tid4 = lane & 3;
    int rsel = lane & 15, csel = (lane >> 4) * 8;
    int wm = (wid & 1) * 64, wn = (wid >> 1) * 32;
    uint32_t as_base = (uint32_t)__cvta_generic_to_shared(As);
    uint32_t bs_base = (uint32_t)__cvta_generic_to_shared(Bs);
    float acc[4][4][4];
    #pragma unroll
    for (int i = 0; i < 4; i++)
        #pragma unroll
        for (int j = 0; j < 4; j++)
            #pragma unroll
            for (int k = 0; k < 4; k++) acc[i][j][k] = 0.f;
    load_stage(0, 0); load_stage(1, 1); load_stage(2, 2);
    #pragma unroll 1
    for (int c = 0; c < nch; c++) {
        int buf = c & 3;
        cpa_wait<2>();
        __syncthreads();
        if (c + 3 < nch) load_stage(c + 3, (c + 3) & 3);
        #pragma unroll
        for (int ks = 0; ks < 32; ks += 16) {
            unsigned a[4][4], bf[2][4];
            #pragma unroll
            for (int mt = 0; mt < 4; mt++) {
                unsigned addr = as_base +
                    (buf * A_ST_SZ + (wm + mt * 16 + rsel) * ASTRIDE + ks + csel) * 2;
                ldsm_x4(addr, a[mt][0], a[mt][1], a[mt][2], a[mt][3]);
            }
            #pragma unroll
            for (int nt2 = 0; nt2 < 2; nt2++) {
                unsigned addr = bs_base +
                    (buf * B_ST_SZ + (ks + rsel) * BSTRIDE + wn + nt2 * 16 + csel) * 2;
                ldsm_x4_t(addr, bf[nt2][0], bf[nt2][1], bf[nt2][2], bf[nt2][3]);
            }
            #pragma unroll
            for (int mt = 0; mt < 4; mt++)
                #pragma unroll
                for (int nt = 0; nt < 4; nt++)
                    mma16816(acc[mt][nt], a[mt], bf[nt >> 1][(nt & 1) * 2],
                             bf[nt >> 1][(nt & 1) * 2 + 1]);
        }
        __syncthreads();
    }
    #pragma unroll
    for (int mt = 0; mt < 4; mt++) {
        int row = bm0 + wm + mt * 16 + gid;
        #pragma unroll
        for (int nt = 0; nt < 4; nt++) {
            int col = bn0 + wn + nt * 8 + 2 * tid4;
            __nv_bfloat16* Cb = C + (long)bz * sC;
            *(__nv_bfloat162*)&Cb[(long)row * N + col] =
                __floats2bfloat162_rn(acc[mt][nt][0] * scale, acc[mt][nt][1] * scale);
            *(__nv_bfloat162*)&Cb[(long)(row + 8) * N + col] =
                __floats2bfloat162_rn(acc[mt][nt][2] * scale, acc[mt][nt][3] * scale);
        }
    }
}

// ================= small kernels =================
__global__ void cvt_kernel(const float* __restrict__ src, __nv_bfloat16* __restrict__ dst, int n) {
    int i = blockIdx.x * blockDim.x + threadIdx.x;
    if (i < n) dst[i] = __float2bfloat16(src[i]);
}
__global__ void zero_kernel(float* p, int n) {
    int i = blockIdx.x * blockDim.x + threadIdx.x;
    if (i < n) p[i] = 0.f;
}

__global__ __launch_bounds__(256) void ln_norm_kernel(const float* __restrict__ x,
                                                      const float* __restrict__ gamma,
                                                      const float* __restrict__ beta,
                                                      __nv_bfloat16* __restrict__ xn) {
    __shared__ float gS[384], bS[384];
    __shared__ float red_s[8][33], red_q[8][33];
    __shared__ float mS[32], rS[32];
    int tid = threadIdx.x;
    int dg = tid >> 5, tn = tid & 31;
    int b = blockIdx.y;
    int n = blockIdx.x * 32 + tn;
    for (int i = tid; i < 384; i += 256) { gS[i] = gamma[i]; bS[i] = beta[i]; }
    const float* xp = x + (long)b * Dd * Nn_ + n;
    float v[48];
    float s = 0.f, q = 0.f;
    #pragma unroll
    for (int i = 0; i < 48; i++) {
        int d = dg + i * 8;
        v[i] = xp[(long)d * Nn_];
        s += v[i]; q += v[i] * v[i];
    }
    red_s[dg][tn] = s; red_q[dg][tn] = q;
    __syncthreads();
    if (dg == 0) {
        float ts = 0.f, tq = 0.f;
        #pragma unroll
        for (int j = 0; j < 8; j++) { ts += red_s[j][tn]; tq += red_q[j][tn]; }
        float mean = ts * (1.0f / Dd);
        float var = tq * (1.0f / Dd) - mean * mean;
        mS[tn] = mean; rS[tn] = rsqrtf(var + EPSLN);
    }
    __syncthreads();
    float mean = mS[tn], rstd = rS[tn];
    __nv_bfloat16* xo = xn + (long)b * Dd * Nn_ + n;
    #pragma unroll
    for (int i = 0; i < 48; i++) {
        int d = dg + i * 8;
        xo[(long)d * Nn_] = __float2bfloat16((v[i] - mean) * rstd * gS[d] + bS[d]);
    }
}

// ---------------- context via mma.sync (k already exp'd) ----------------
__global__ __launch_bounds__(256) void context_mma_kernel(const __nv_bfloat16* __restrict__ kv,
                                                          float* __restrict__ ctx_part) {
    __shared__ __align__(16) __nv_bfloat16 Ks[2][64 * 72];
    __shared__ __align__(16) __nv_bfloat16 Vs[2][64 * 72];
    const int LEN = Nn_ / NSPLIT;
    int sp = blockIdx.x, bh = blockIdx.y;
    int b = bh >> 3, h = bh & 7;
    const __nv_bfloat16* kb = kv + ((long)b * 1024 + h * 64) * Nn_;
    const __nv_bfloat16* vb = kv + ((long)b * 1024 + 512 + h * 64) * Nn_;
    int tid = threadIdx.x, lane = tid & 31, wid = tid >> 5;
    int lr = tid >> 3, lc = (tid & 7) * 8;
    int n0 = sp * LEN;
    int gid = lane >> 2, tid4 = lane & 3;
    int rsel = lane & 15, csel = (lane >> 4) * 8;
    int wm = (wid & 1) * 32, wn = (wid >> 1) * 16;
    float acc[2][2][4];
    #pragma unroll
    for (int i = 0; i < 2; i++)
        #pragma unroll
        for (int j = 0; j < 2; j++)
            #pragma unroll
            for (int k = 0; k < 4; k++) acc[i][j][k] = 0.f;
    uint4 k0v, k1v, v0v, v1v;
    const int NCH = LEN / 64;
    int so = lr * 72 + lc;
    k0v = *(const uint4*)(kb + (long)lr * Nn_ + n0 + lc);
    k1v = *(const uint4*)(kb + (long)(lr + 32) * Nn_ + n0 + lc);
    v0v = *(const uint4*)(vb + (long)lr * Nn_ + n0 + lc);
    v1v = *(const uint4*)(vb + (long)(lr + 32) * Nn_ + n0 + lc);
    *(uint4*)&Ks[0][so] = k0v; *(uint4*)&Ks[0][so + 32 * 72] = k1v;
    *(uint4*)&Vs[0][so] = v0v; *(uint4*)&Vs[0][so + 32 * 72] = v1v;
    __syncthreads();
    for (int c = 0; c < NCH; c++) {
        int buf = c & 1;
        if (c + 1 < NCH) {
            int off = n0 + (c + 1) * 64 + lc;
            k0v = *(const uint4*)(kb + (long)lr * Nn_ + off);
            k1v = *(const uint4*)(kb + (long)(lr + 32) * Nn_ + off);
            v0v = *(const uint4*)(vb + (long)lr * Nn_ + off);
            v1v = *(const uint4*)(vb + (long)(lr + 32) * Nn_ + off);
        }
        #pragma unroll
        for (int ks = 0; ks < 64; ks += 16) {
            unsigned a[2][4], bf[4];
            #pragma unroll
            for (int mt = 0; mt < 2; mt++) {
                unsigned addr = (unsigned)__cvta_generic_to_shared(
                    &Ks[buf][(wm + mt * 16 + rsel) * 72 + ks + csel]);
                ldsm_x4(addr, a[mt][0], a[mt][1], a[mt][2], a[mt][3]);
            }
            {
                unsigned addr = (unsigned)__cvta_generic_to_shared(
                    &Vs[buf][(wn + rsel) * 72 + ks + csel]);
                ldsm_x4(addr, bf[0], bf[1], bf[2], bf[3]);
            }
            #pragma unroll
            for (int mt = 0; mt < 2; mt++)
                #pragma unroll
                for (int nt = 0; nt < 2; nt++)
                    mma16816(acc[mt][nt], a[mt], bf[nt], bf[nt + 2]);
        }
        if (c + 1 < NCH) {
            int nb = (c + 1) & 1;
            *(uint4*)&Ks[nb][so] = k0v; *(uint4*)&Ks[nb][so + 32 * 72] = k1v;
            *(uint4*)&Vs[nb][so] = v0v; *(uint4*)&Vs[nb][so + 32 * 72] = v1v;
        }
        __syncthreads();
    }
    float* cp = ctx_part + ((long)sp * 128 + bh) * 4096;
    #pragma unroll
    for (int mt = 0; mt < 2; mt++) {
        int row = wm + mt * 16 + gid;
        #pragma unroll
        for (int nt = 0; nt < 2; nt++) {
            int col = wn + nt * 8 + 2 * tid4;
            *(float2*)&cp[row * 64 + col] = make_float2(acc[mt][nt][0], acc[mt][nt][1]);
            *(float2*)&cp[(row + 8) * 64 + col] = make_float2(acc[mt][nt][2], acc[mt][nt][3]);
        }
    }
}

// ------------- T build -------------
__global__ __launch_bounds__(256) void build_T_kernel(const float* __restrict__ ctx_part,
                                                      const float* __restrict__ rowsum,
                                                      const float* __restrict__ wout,
                                                      __nv_bfloat16* __restrict__ T) {
    int bh = blockIdx.x;
    int b = bh >> 3, h = bh & 7;
    __shared__ float ctxS[64][65];
    __shared__ float wS[64][65];
    int tid = threadIdx.x;
    #pragma unroll
    for (int i = 0; i < 16; i++) {
        int idx = tid + i * 256;
        int d = idx >> 6;
        float s = 0.f;
        #pragma unroll
        for (int sp = 0; sp < NSPLIT; sp++)
            s += ctx_part[((long)sp * 128 + bh) * 4096 + idx];
        ctxS[d][idx & 63] = s / rowsum[b * 512 + h * 64 + d];
    }
    __syncthreads();
    __nv_bfloat16* Tb = T + (long)b * 384 * 512;
    for (int c = 0; c < 6; c++) {
        #pragma unroll
        for (int i = 0; i < 16; i++) {
            int idx = tid + i * 256;
            int dr = idx >> 6, e = idx & 63;
            wS[dr][e] = wout[(long)(c * 64 + dr) * Hh + h * 64 + e];
        }
        __syncthreads();
        #pragma unroll
        for (int i = 0; i < 16; i++) {
            int idx = tid + i * 256;
            int dl = idx >> 6, dd = idx & 63;
            float s = 0.f;
            #pragma unroll
            for (int e = 0; e < 64; e++)
                s += wS[dl][e] * ctxS[dd][e];
            Tb[(long)(c * 64 + dl) * 512 + h * 64 + dd] = __float2bfloat16(s);
        }
        __syncthreads();
    }
}

// -------------------------------------------------------------------------
extern "C" void kernel_launch(void* const* d_in, const int* in_sizes, int n_in,
                              void* d_out, int out_size) {
    (void)in_sizes; (void)n_in; (void)out_size;
    const float* x     = (const float*)d_in[0];
    const float* gam   = (const float*)d_in[1];
    const float* bet   = (const float*)d_in[2];
    const float* w_qkv = (const float*)d_in[3];
    const float* w_out = (const float*)d_in[4];
    const float* b_out = (const float*)d_in[5];
    float* out = (float*)d_out;

    __nv_bfloat16 *p_xn, *p_kv, *p_T, *p_wf, *p_wq;
    float *p_ctxp, *p_rowsum;
    cudaGetSymbolAddress((void**)&p_xn,     g_xn);
    cudaGetSymbolAddress((void**)&p_kv,     g_kv);
    cudaGetSymbolAddress((void**)&p_ctxp,   g_ctxpart);
    cudaGetSymbolAddress((void**)&p_rowsum, g_rowsum);
    cudaGetSymbolAddress((void**)&p_T,      g_T);
    cudaGetSymbolAddress((void**)&p_wf,     g_wf);
    cudaGetSymbolAddress((void**)&p_wq,     g_wqkv_bf);

    cudaFuncSetAttribute(gemm_w64<0>, cudaFuncAttributeMaxDynamicSharedMemorySize, GSMEM_BYTES);
    cudaFuncSetAttribute(gemm_w64<1>, cudaFuncAttributeMaxDynamicSharedMemorySize, GSMEM_BYTES);
    cudaFuncSetAttribute(gemm_small, cudaFuncAttributeMaxDynamicSharedMemorySize, GSMEM_BYTES);

    // 0. prep
    cvt_kernel<<<(1536 * 384 + 255) / 256, 256>>>(w_qkv, p_wq, 1536 * 384);
    zero_kernel<<<(Bb * 512 + 255) / 256, 256>>>(p_rowsum, Bb * 512);

    // 1. LN -> bf16 x_norm
    ln_norm_kernel<<<dim3(Nn_ / 32, Bb), 256>>>(x, gam, bet, p_xn);

    // 2. kv = W_kv @ xn (M=1024, one launch); k rows exp'd + rowsum atomics
    gemm_w64<0><<<dim3(8, 64, Bb), 128, GSMEM_BYTES>>>(
        p_wq + (long)512 * Dd, p_xn, p_kv, Dd, Nn_,
        0L, (long)Dd * Nn_, (long)1024 * Nn_,
        nullptr, nullptr, 0L, p_rowsum);

    // 3. partial contexts
    context_mma_kernel<<<dim3(NSPLIT, 128), 256>>>(p_kv, p_ctxp);

    // 4. T
    build_T_kernel<<<128, 256>>>(p_ctxp, p_rowsum, w_out, p_T);

    // 5. W_final[b] = SCALE * T[b] @ W_q
    gemm_small<<<dim3(3, 3, Bb), 256, GSMEM_BYTES>>>(
        p_T, p_wq, p_wf, 512, 384,
        (long)384 * 512, 0L, (long)384 * 384, SCALE);

    // 6. out = W_final[b] @ xn + b_out + x
    gemm_w64<1><<<dim3(3, 64, Bb), 128, GSMEM_BYTES>>>(
        p_wf, p_xn, out, Dd, Nn_,
        (long)384 * 384, (long)Dd * Nn_, (long)Dd * Nn_,
        b_out, x, (long)Dd * Nn_, nullptr);
}

// round 13
// speedup vs baseline: 1.0616x; 1.0029x over previous
#include <cuda_runtime.h>
#include <cuda_bf16.h>
#include <math.h>
#include <stdint.h>

#define Bb 16
#define Dd 384
#define Nn_ 8192
#define Hh 512
#define SCALE 0.125f
#define EPSLN 1e-5f
#define NSPLIT 16

// ---------------- static scratch ----------------
__device__ __nv_bfloat16 g_xn[(long)Bb * Dd * Nn_];     // LN(x), bf16, [b][d][n]
__device__ __nv_bfloat16 g_kv[(long)Bb * 1024 * Nn_];   // rows 0..511 exp(k), 512..1023 v
__device__ float         g_ctxpart[(long)NSPLIT * 128 * 4096];
__device__ float         g_rowsum[Bb * 512];
__device__ __nv_bfloat16 g_T[(long)Bb * 384 * 512];
__device__ __nv_bfloat16 g_wf[(long)Bb * 384 * 384];
__device__ __nv_bfloat16 g_wqkv_bf[1536 * 384];

// ---------------- mma.sync helpers ----------------
__device__ __forceinline__ void ldsm_x4(unsigned addr, unsigned &r0, unsigned &r1,
                                        unsigned &r2, unsigned &r3) {
    asm volatile("ldmatrix.sync.aligned.m8n8.x4.shared.b16 {%0,%1,%2,%3}, [%4];\n"
                 : "=r"(r0), "=r"(r1), "=r"(r2), "=r"(r3) : "r"(addr));
}
__device__ __forceinline__ void ldsm_x4_t(unsigned addr, unsigned &r0, unsigned &r1,
                                          unsigned &r2, unsigned &r3) {
    asm volatile("ldmatrix.sync.aligned.m8n8.x4.trans.shared.b16 {%0,%1,%2,%3}, [%4];\n"
                 : "=r"(r0), "=r"(r1), "=r"(r2), "=r"(r3) : "r"(addr));
}
__device__ __forceinline__ void mma16816(float *c, const unsigned *a, unsigned b0, unsigned b1) {
    asm volatile("mma.sync.aligned.m16n8k16.row.col.f32.bf16.bf16.f32 "
                 "{%0,%1,%2,%3}, {%4,%5,%6,%7}, {%8,%9}, {%0,%1,%2,%3};\n"
                 : "+f"(c[0]), "+f"(c[1]), "+f"(c[2]), "+f"(c[3])
                 : "r"(a[0]), "r"(a[1]), "r"(a[2]), "r"(a[3]), "r"(b0), "r"(b1));
}
__device__ __forceinline__ void cpa16(uint32_t s, const void* g) {
    asm volatile("cp.async.cg.shared.global [%0], [%1], 16;" :: "r"(s), "l"(g));
}
__device__ __forceinline__ void cpa_commit() { asm volatile("cp.async.commit_group;" ::: "memory"); }
template<int NN>
__device__ __forceinline__ void cpa_wait() { asm volatile("cp.async.wait_group %0;" :: "n"(NN) : "memory"); }

#define ASTRIDE 40
#define BSTRIDE 136
#define A_ST_SZ (128 * ASTRIDE)
#define B_ST_SZ (32 * BSTRIDE)
#define GSMEM_BYTES ((4 * A_ST_SZ + 4 * B_ST_SZ) * 2)

// ================= 128x128 GEMM, 4 warps of 64x64, 4-stage cp.async =======
// Intra-chunk A-fragment pipelining: ldsmA(ks16) hoisted above MMA(ks0).
// EPI 0: bf16 out; rows<512 exp() + rowsum atomics  (fused kv-GEMM)
// EPI 1: fp32 out + bias[row] + resid               (GEMM7)
template<int EPI>
__global__ __launch_bounds__(128, 2)
void gemm_w64(const __nv_bfloat16* __restrict__ A, const __nv_bfloat16* __restrict__ B,
              void* __restrict__ Cv, int K, int N,
              long sA, long sB, long sC,
              const float* __restrict__ bias, const float* __restrict__ resid, long sRes,
              float* __restrict__ rowsum) {
    extern __shared__ __nv_bfloat16 smem[];
    __nv_bfloat16* As = smem;
    __nv_bfloat16* Bs = smem + 4 * A_ST_SZ;

    int tid = threadIdx.x, lane = tid & 31, wid = tid >> 5;
    int bz = blockIdx.z;
    const __nv_bfloat16* Ab = A + (long)bz * sA;
    const __nv_bfloat16* Bp = B + (long)bz * sB;
    int bm0 = blockIdx.x * 128, bn0 = blockIdx.y * 128;

    uint32_t as_base = (uint32_t)__cvta_generic_to_shared(As);
    uint32_t bs_base = (uint32_t)__cvta_generic_to_shared(Bs);

    int nch = K / 32;
    auto load_stage = [&](int c, int buf) {
        int k0 = c * 32;
        #pragma unroll
        for (int i = 0; i < 4; i++) {          // A: 128 rows x 32 halves
            int v = i * 128 + tid;
            int row = v >> 2, kq = v & 3;
            cpa16(as_base + (uint32_t)(buf * A_ST_SZ + row * ASTRIDE + kq * 8) * 2,
                  Ab + (long)(bm0 + row) * K + k0 + kq * 8);
        }
        #pragma unroll
        for (int i = 0; i < 4; i++) {          // B: 32 rows x 128 halves
            int v = i * 128 + tid;
            int row = v >> 4, q = v & 15;
            cpa16(bs_base + (uint32_t)(buf * B_ST_SZ + row * BSTRIDE + q * 8) * 2,
                  Bp + (long)(k0 + row) * N + bn0 + q * 8);
        }
        cpa_commit();
    };

    int gid = lane >> 2, tid4 = lane & 3;
    int rsel = lane & 15, csel = (lane >> 4) * 8;
    int wm = (wid & 1) * 64, wn = (wid >> 1) * 64;

    float acc[4][8][4];
    #pragma unroll
    for (int i = 0; i < 4; i++)
        #pragma unroll
        for (int j = 0; j < 8; j++)
            #pragma unroll
            for (int k = 0; k < 4; k++) acc[i][j][k] = 0.f;

    load_stage(0, 0); load_stage(1, 1); load_stage(2, 2);

    #pragma unroll 1
    for (int c = 0; c < nch; c++) {
        int buf = c & 3;
        cpa_wait<2>();
        __syncthreads();
        if (c + 3 < nch) load_stage(c + 3, (c + 3) & 3);

        unsigned a0[4][4], a1[4][4], bf[4][4];
        // ldsm A (ks=0)
        #pragma unroll
        for (int mt = 0; mt < 4; mt++) {
            unsigned addr = as_base +
                (uint32_t)(buf * A_ST_SZ + (wm + mt * 16 + rsel) * ASTRIDE + csel) * 2;
            ldsm_x4(addr, a0[mt][0], a0[mt][1], a0[mt][2], a0[mt][3]);
        }
        // ldsm B (ks=0)
        #pragma unroll
        for (int nt2 = 0; nt2 < 4; nt2++) {
            unsigned addr = bs_base +
                (uint32_t)(buf * B_ST_SZ + rsel * BSTRIDE + wn + nt2 * 16 + csel) * 2;
            ldsm_x4_t(addr, bf[nt2][0], bf[nt2][1], bf[nt2][2], bf[nt2][3]);
        }
        // ldsm A (ks=16) — latency hidden behind MMA(ks=0)
        #pragma unroll
        for (int mt = 0; mt < 4; mt++) {
            unsigned addr = as_base +
                (uint32_t)(buf * A_ST_SZ + (wm + mt * 16 + rsel) * ASTRIDE + 16 + csel) * 2;
            ldsm_x4(addr, a1[mt][0], a1[mt][1], a1[mt][2], a1[mt][3]);
        }
        // MMA (ks=0)
        #pragma unroll
        for (int mt = 0; mt < 4; mt++)
            #pragma unroll
            for (int nt = 0; nt < 8; nt++)
                mma16816(acc[mt][nt], a0[mt], bf[nt >> 1][(nt & 1) * 2],
                         bf[nt >> 1][(nt & 1) * 2 + 1]);
        // ldsm B (ks=16)
        #pragma unroll
        for (int nt2 = 0; nt2 < 4; nt2++) {
            unsigned addr = bs_base +
                (uint32_t)(buf * B_ST_SZ + (16 + rsel) * BSTRIDE + wn + nt2 * 16 + csel) * 2;
            ldsm_x4_t(addr, bf[nt2][0], bf[nt2][1], bf[nt2][2], bf[nt2][3]);
        }
        // MMA (ks=16)
        #pragma unroll
        for (int mt = 0; mt < 4; mt++)
            #pragma unroll
            for (int nt = 0; nt < 8; nt++)
                mma16816(acc[mt][nt], a1[mt], bf[nt >> 1][(nt & 1) * 2],
                         bf[nt >> 1][(nt & 1) * 2 + 1]);
        __syncthreads();
    }

    if (EPI == 0) {
        __nv_bfloat16* Cb = (__nv_bfloat16*)Cv + (long)bz * sC;
        bool isk = (bm0 < 512);
        float rs[8];
        #pragma unroll
        for (int i = 0; i < 8; i++) rs[i] = 0.f;
        #pragma unroll
        for (int mt = 0; mt < 4; mt++) {
            int row = bm0 + wm + mt * 16 + gid;
            #pragma unroll
            for (int nt = 0; nt < 8; nt++) {
                int col = bn0 + wn + nt * 8 + 2 * tid4;
                float c0 = acc[mt][nt][0], c1 = acc[mt][nt][1];
                float c2 = acc[mt][nt][2], c3 = acc[mt][nt][3];
                if (isk) {
                    c0 = __expf(c0); c1 = __expf(c1);
                    c2 = __expf(c2); c3 = __expf(c3);
                    rs[mt * 2] += c0 + c1;
                    rs[mt * 2 + 1] += c2 + c3;
                }
                *(__nv_bfloat162*)&Cb[(long)row * N + col] = __floats2bfloat162_rn(c0, c1);
                *(__nv_bfloat162*)&Cb[(long)(row + 8) * N + col] = __floats2bfloat162_rn(c2, c3);
            }
        }
        if (isk) {
            #pragma unroll
            for (int i = 0; i < 8; i++) {
                rs[i] += __shfl_xor_sync(0xffffffffu, rs[i], 1);
                rs[i] += __shfl_xor_sync(0xffffffffu, rs[i], 2);
            }
            if (tid4 == 0) {
                #pragma unroll
                for (int mt = 0; mt < 4; mt++) {
                    int row = bm0 + wm + mt * 16 + gid;
                    atomicAdd(&rowsum[bz * 512 + row], rs[mt * 2]);
                    atomicAdd(&rowsum[bz * 512 + row + 8], rs[mt * 2 + 1]);
                }
            }
        }
    } else {
        float* Cf = (float*)Cv + (long)bz * sC;
        const float* rp = resid + (long)bz * sRes;
        #pragma unroll
        for (int mt = 0; mt < 4; mt++) {
            int row = bm0 + wm + mt * 16 + gid;
            float b1 = bias[row], b2 = bias[row + 8];
            #pragma unroll
            for (int nt = 0; nt < 8; nt++) {
                int col = bn0 + wn + nt * 8 + 2 * tid4;
                float2 r1 = *(const float2*)&rp[(long)row * N + col];
                float2 r2 = *(const float2*)&rp[(long)(row + 8) * N + col];
                float2 o1 = make_float2(acc[mt][nt][0] + b1 + r1.x, acc[mt][nt][1] + b1 + r1.y);
                float2 o2 = make_float2(acc[mt][nt][2] + b2 + r2.x, acc[mt][nt][3] + b2 + r2.y);
                *(float2*)&Cf[(long)row * N + col] = o1;
                *(float2*)&Cf[(long)(row + 8) * N + col] = o2;
            }
        }
    }
}

// ================= R4 128x128 8-warp GEMM (GEMM6 only) =================
__global__ __launch_bounds__(256)
void gemm_small(const __nv_bfloat16* __restrict__ A, const __nv_bfloat16* __restrict__ B,
                __nv_bfloat16* __restrict__ C, int K, int N,
                long sA, long sB, long sC, float scale) {
    extern __shared__ __nv_bfloat16 smem[];
    __nv_bfloat16* As = smem;
    __nv_bfloat16* Bs = smem + 4 * A_ST_SZ;
    int tid = threadIdx.x, lane = tid & 31, wid = tid >> 5;
    int bz = blockIdx.z;
    const __nv_bfloat16* Ab = A + (long)bz * sA;
    const __nv_bfloat16* Bp = B + (long)bz * sB;
    int bm0 = blockIdx.x * 128, bn0 = blockIdx.y * 128;
    int am = tid >> 2, akq = tid & 3;
    int bk = tid >> 4, bnq = tid & 15;
    const __nv_bfloat16* Ag0 = Ab + (long)(bm0 + am) * K + akq * 8;
    const __nv_bfloat16* Ag1 = Ag0 + (long)64 * K;
    const __nv_bfloat16* Bg0 = Bp + (long)bk * N + bn0 + bnq * 8;
    const __nv_bfloat16* Bg1 = Bg0 + (long)16 * N;
    uint32_t a_s0 = (uint32_t)__cvta_generic_to_shared(&As[am * ASTRIDE + akq * 8]);
    uint32_t a_s1 = (uint32_t)__cvta_generic_to_shared(&As[(am + 64) * ASTRIDE + akq * 8]);
    uint32_t b_s0 = (uint32_t)__cvta_generic_to_shared(&Bs[bk * BSTRIDE + bnq * 8]);
    uint32_t b_s1 = (uint32_t)__cvta_generic_to_shared(&Bs[(bk + 16) * BSTRIDE + bnq * 8]);
    int nch = K / 32;
    auto load_stage = [&](int c, int buf) {
        int k0 = c * 32;
        cpa16(a_s0 + buf * A_ST_SZ * 2, Ag0 + k0);
        cpa16(a_s1 + buf * A_ST_SZ * 2, Ag1 + k0);
        cpa16(b_s0 + buf * B_ST_SZ * 2, Bg0 + (long)k0 * N);
        cpa16(b_s1 + buf * B_ST_SZ * 2, Bg1 + (long)k0 * N);
        cpa_commit();
    };
    int gid = lane >> 2, tid4 = lane & 3;
    int rsel = lane & 15, csel = (lane >> 4) * 8;
    int wm = (wid & 1) * 64, wn = (wid >> 1) * 32;
    uint32_t as_base = (uint32_t)__cvta_generic_to_shared(As);
    uint32_t bs_base = (uint32_t)__cvta_generic_to_shared(Bs);
    float acc[4][4][4];
    #pragma unroll
    for (int i = 0; i < 4; i++)
        #pragma unroll
        for (int j = 0; j < 4; j++)
            #pragma unroll
            for (int k = 0; k < 4; k++) acc[i][j][k] = 0.f;
    load_stage(0, 0); load_stage(1, 1); load_stage(2, 2);
    #pragma unroll 1
    for (int c = 0; c < nch; c++) {
        int buf = c & 3;
        cpa_wait<2>();
        __syncthreads();
        if (c + 3 < nch) load_stage(c + 3, (c + 3) & 3);
        #pragma unroll
        for (int ks = 0; ks < 32; ks += 16) {
            unsigned a[4][4], bf[2][4];
            #pragma unroll
            for (int mt = 0; mt < 4; mt++) {
                unsigned addr = as_base +
                    (buf * A_ST_SZ + (wm + mt * 16 + rsel) * ASTRIDE + ks + csel) * 2;
                ldsm_x4(addr, a[mt][0], a[mt][1], a[mt][2], a[mt][3]);
            }
            #pragma unroll
            for (int nt2 = 0; nt2 < 2; nt2++) {
                unsigned addr = bs_base +
                    (buf * B_ST_SZ + (ks + rsel) * BSTRIDE + wn + nt2 * 16 + csel) * 2;
                ldsm_x4_t(addr, bf[nt2][0], bf[nt2][1], bf[nt2][2], bf[nt2][3]);
            }
            #pragma unroll
            for (int mt = 0; mt < 4; mt++)
                #pragma unroll
                for (int nt = 0; nt < 4; nt++)
                    mma16816(acc[mt][nt], a[mt], bf[nt >> 1][(nt & 1) * 2],
                             bf[nt >> 1][(nt & 1) * 2 + 1]);
        }
        __syncthreads();
    }
    #pragma unroll
    for (int mt = 0; mt < 4; mt++) {
        int row = bm0 + wm + mt * 16 + gid;
        #pragma unroll
        for (int nt = 0; nt < 4; nt++) {
            int col = bn0 + wn + nt * 8 + 2 * tid4;
            __nv_bfloat16* Cb = C + (long)bz * sC;
            *(__nv_bfloat162*)&Cb[(long)row * N + col] =
                __floats2bfloat162_rn(acc[mt][nt][0] * scale, acc[mt][nt][1] * scale);
            *(__nv_bfloat162*)&Cb[(long)(row + 8) * N + col] =
                __floats2bfloat162_rn(acc[mt][nt][2] * scale, acc[mt][nt][3] * scale);
        }
    }
}

// ================= small kernels =================
__global__ void cvt_kernel(const float* __restrict__ src, __nv_bfloat16* __restrict__ dst, int n) {
    int i = blockIdx.x * blockDim.x + threadIdx.x;
    if (i < n) dst[i] = __float2bfloat16(src[i]);
}
__global__ void zero_kernel(float* p, int n) {
    int i = blockIdx.x * blockDim.x + threadIdx.x;
    if (i < n) p[i] = 0.f;
}

__global__ __launch_bounds__(256) void ln_norm_kernel(const float* __restrict__ x,
                                                      const float* __restrict__ gamma,
                                                      const float* __restrict__ beta,
                                                      __nv_bfloat16* __restrict__ xn) {
    __shared__ float gS[384], bS[384];
    __shared__ float red_s[8][33], red_q[8][33];
    __shared__ float mS[32], rS[32];
    int tid = threadIdx.x;
    int dg = tid >> 5, tn = tid & 31;
    int b = blockIdx.y;
    int n = blockIdx.x * 32 + tn;
    for (int i = tid; i < 384; i += 256) { gS[i] = gamma[i]; bS[i] = beta[i]; }
    const float* xp = x + (long)b * Dd * Nn_ + n;
    float v[48];
    float s = 0.f, q = 0.f;
    #pragma unroll
    for (int i = 0; i < 48; i++) {
        int d = dg + i * 8;
        v[i] = xp[(long)d * Nn_];
        s += v[i]; q += v[i] * v[i];
    }
    red_s[dg][tn] = s; red_q[dg][tn] = q;
    __syncthreads();
    if (dg == 0) {
        float ts = 0.f, tq = 0.f;
        #pragma unroll
        for (int j = 0; j < 8; j++) { ts += red_s[j][tn]; tq += red_q[j][tn]; }
        float mean = ts * (1.0f / Dd);
        float var = tq * (1.0f / Dd) - mean * mean;
        mS[tn] = mean; rS[tn] = rsqrtf(var + EPSLN);
    }
    __syncthreads();
    float mean = mS[tn], rstd = rS[tn];
    __nv_bfloat16* xo = xn + (long)b * Dd * Nn_ + n;
    #pragma unroll
    for (int i = 0; i < 48; i++) {
        int d = dg + i * 8;
        xo[(long)d * Nn_] = __float2bfloat16((v[i] - mean) * rstd * gS[d] + bS[d]);
    }
}

// ---------------- context via mma.sync (k already exp'd) ----------------
__global__ __launch_bounds__(256) void context_mma_kernel(const __nv_bfloat16* __restrict__ kv,
                                                          float* __restrict__ ctx_part) {
    __shared__ __align__(16) __nv_bfloat16 Ks[2][64 * 72];
    __shared__ __align__(16) __nv_bfloat16 Vs[2][64 * 72];
    const int LEN = Nn_ / NSPLIT;
    int sp = blockIdx.x, bh = blockIdx.y;
    int b = bh >> 3, h = bh & 7;
    const __nv_bfloat16* kb = kv + ((long)b * 1024 + h * 64) * Nn_;
    const __nv_bfloat16* vb = kv + ((long)b * 1024 + 512 + h * 64) * Nn_;
    int tid = threadIdx.x, lane = tid & 31, wid = tid >> 5;
    int lr = tid >> 3, lc = (tid & 7) * 8;
    int n0 = sp * LEN;
    int gid = lane >> 2, tid4 = lane & 3;
    int rsel = lane & 15, csel = (lane >> 4) * 8;
    int wm = (wid & 1) * 32, wn = (wid >> 1) * 16;
    float acc[2][2][4];
    #pragma unroll
    for (int i = 0; i < 2; i++)
        #pragma unroll
        for (int j = 0; j < 2; j++)
            #pragma unroll
            for (int k = 0; k < 4; k++) acc[i][j][k] = 0.f;
    uint4 k0v, k1v, v0v, v1v;
    const int NCH = LEN / 64;
    int so = lr * 72 + lc;
    k0v = *(const uint4*)(kb + (long)lr * Nn_ + n0 + lc);
    k1v = *(const uint4*)(kb + (long)(lr + 32) * Nn_ + n0 + lc);
    v0v = *(const uint4*)(vb + (long)lr * Nn_ + n0 + lc);
    v1v = *(const uint4*)(vb + (long)(lr + 32) * Nn_ + n0 + lc);
    *(uint4*)&Ks[0][so] = k0v; *(uint4*)&Ks[0][so + 32 * 72] = k1v;
    *(uint4*)&Vs[0][so] = v0v; *(uint4*)&Vs[0][so + 32 * 72] = v1v;
    __syncthreads();
    for (int c = 0; c < NCH; c++) {
        int buf = c & 1;
        if (c + 1 < NCH) {
            int off = n0 + (c + 1) * 64 + lc;
            k0v = *(const uint4*)(kb + (long)lr * Nn_ + off);
            k1v = *(const uint4*)(kb + (long)(lr + 32) * Nn_ + off);
            v0v = *(const uint4*)(vb + (long)lr * Nn_ + off);
            v1v = *(const uint4*)(vb + (long)(lr + 32) * Nn_ + off);
        }
        #pragma unroll
        for (int ks = 0; ks < 64; ks += 16) {
            unsigned a[2][4], bf[4];
            #pragma unroll
            for (int mt = 0; mt < 2; mt++) {
                unsigned addr = (unsigned)__cvta_generic_to_shared(
                    &Ks[buf][(wm + mt * 16 + rsel) * 72 + ks + csel]);
                ldsm_x4(addr, a[mt][0], a[mt][1], a[mt][2], a[mt][3]);
            }
            {
                unsigned addr = (unsigned)__cvta_generic_to_shared(
                    &Vs[buf][(wn + rsel) * 72 + ks + csel]);
                ldsm_x4(addr, bf[0], bf[1], bf[2], bf[3]);
            }
            #pragma unroll
            for (int mt = 0; mt < 2; mt++)
                #pragma unroll
                for (int nt = 0; nt < 2; nt++)
                    mma16816(acc[mt][nt], a[mt], bf[nt], bf[nt + 2]);
        }
        if (c + 1 < NCH) {
            int nb = (c + 1) & 1;
            *(uint4*)&Ks[nb][so] = k0v; *(uint4*)&Ks[nb][so + 32 * 72] = k1v;
            *(uint4*)&Vs[nb][so] = v0v; *(uint4*)&Vs[nb][so + 32 * 72] = v1v;
        }
        __syncthreads();
    }
    float* cp = ctx_part + ((long)sp * 128 + bh) * 4096;
    #pragma unroll
    for (int mt = 0; mt < 2; mt++) {
        int row = wm + mt * 16 + gid;
        #pragma unroll
        for (int nt = 0; nt < 2; nt++) {
            int col = wn + nt * 8 + 2 * tid4;
            *(float2*)&cp[row * 64 + col] = make_float2(acc[mt][nt][0], acc[mt][nt][1]);
            *(float2*)&cp[(row + 8) * 64 + col] = make_float2(acc[mt][nt][2], acc[mt][nt][3]);
        }
    }
}

// ------------- T build -------------
__global__ __launch_bounds__(256) void build_T_kernel(const float* __restrict__ ctx_part,
                                                      const float* __restrict__ rowsum,
                                                      const float* __restrict__ wout,
                                                      __nv_bfloat16* __restrict__ T) {
    int bh = blockIdx.x;
    int b = bh >> 3, h = bh & 7;
    __shared__ float ctxS[64][65];
    __shared__ float wS[64][65];
    int tid = threadIdx.x;
    #pragma unroll
    for (int i = 0; i < 16; i++) {
        int idx = tid + i * 256;
        int d = idx >> 6;
        float s = 0.f;
        #pragma unroll
        for (int sp = 0; sp < NSPLIT; sp++)
            s += ctx_part[((long)sp * 128 + bh) * 4096 + idx];
        ctxS[d][idx & 63] = s / rowsum[b * 512 + h * 64 + d];
    }
    __syncthreads();
    __nv_bfloat16* Tb = T + (long)b * 384 * 512;
    for (int c = 0; c < 6; c++) {
        #pragma unroll
        for (int i = 0; i < 16; i++) {
            int idx = tid + i * 256;
            int dr = idx >> 6, e = idx & 63;
            wS[dr][e] = wout[(long)(c * 64 + dr) * Hh + h * 64 + e];
        }
        __syncthreads();
        #pragma unroll
        for (int i = 0; i < 16; i++) {
            int idx = tid + i * 256;
            int dl = idx >> 6, dd = idx & 63;
            float s = 0.f;
            #pragma unroll
            for (int e = 0; e < 64; e++)
                s += wS[dl][e] * ctxS[dd][e];
            Tb[(long)(c * 64 + dl) * 512 + h * 64 + dd] = __float2bfloat16(s);
        }
        __syncthreads();
    }
}

// -------------------------------------------------------------------------
extern "C" void kernel_launch(void* const* d_in, const int* in_sizes, int n_in,
                              void* d_out, int out_size) {
    (void)in_sizes; (void)n_in; (void)out_size;
    const float* x     = (const float*)d_in[0];
    const float* gam   = (const float*)d_in[1];
    const float* bet   = (const float*)d_in[2];
    const float* w_qkv = (const float*)d_in[3];
    const float* w_out = (const float*)d_in[4];
    const float* b_out = (const float*)d_in[5];
    float* out = (float*)d_out;

    __nv_bfloat16 *p_xn, *p_kv, *p_T, *p_wf, *p_wq;
    float *p_ctxp, *p_rowsum;
    cudaGetSymbolAddress((void**)&p_xn,     g_xn);
    cudaGetSymbolAddress((void**)&p_kv,     g_kv);
    cudaGetSymbolAddress((void**)&p_ctxp,   g_ctxpart);
    cudaGetSymbolAddress((void**)&p_rowsum, g_rowsum);
    cudaGetSymbolAddress((void**)&p_T,      g_T);
    cudaGetSymbolAddress((void**)&p_wf,     g_wf);
    cudaGetSymbolAddress((void**)&p_wq,     g_wqkv_bf);

    cudaFuncSetAttribute(gemm_w64<0>, cudaFuncAttributeMaxDynamicSharedMemorySize, GSMEM_BYTES);
    cudaFuncSetAttribute(gemm_w64<1>, cudaFuncAttributeMaxDynamicSharedMemorySize, GSMEM_BYTES);
    cudaFuncSetAttribute(gemm_small, cudaFuncAttributeMaxDynamicSharedMemorySize, GSMEM_BYTES);

    // 0. prep
    cvt_kernel<<<(1536 * 384 + 255) / 256, 256>>>(w_qkv, p_wq, 1536 * 384);
    zero_kernel<<<(Bb * 512 + 255) / 256, 256>>>(p_rowsum, Bb * 512);

    // 1. LN -> bf16 x_norm
    ln_norm_kernel<<<dim3(Nn_ / 32, Bb), 256>>>(x, gam, bet, p_xn);

    // 2. kv = W_kv @ xn (M=1024, one launch); k rows exp'd + rowsum atomics
    gemm_w64<0><<<dim3(8, 64, Bb), 128, GSMEM_BYTES>>>(
        p_wq + (long)512 * Dd, p_xn, p_kv, Dd, Nn_,
        0L, (long)Dd * Nn_, (long)1024 * Nn_,
        nullptr, nullptr, 0L, p_rowsum);

    // 3. partial contexts
    context_mma_kernel<<<dim3(NSPLIT, 128), 256>>>(p_kv, p_ctxp);

    // 4. T
    build_T_kernel<<<128, 256>>>(p_ctxp, p_rowsum, w_out, p_T);

    // 5. W_final[b] = SCALE * T[b] @ W_q
    gemm_small<<<dim3(3, 3, Bb), 256, GSMEM_BYTES>>>(
        p_T, p_wq, p_wf, 512, 384,
        (long)384 * 512, 0L, (long)384 * 384, SCALE);

    // 6. out = W_final[b] @ xn + b_out + x
    gemm_w64<1><<<dim3(3, 64, Bb), 128, GSMEM_BYTES>>>(
        p_wf, p_xn, out, Dd, Nn_,
        (long)384 * 384, (long)Dd * Nn_, (long)Dd * Nn_,
        b_out, x, (long)Dd * Nn_, nullptr);
}

// round 15
// speedup vs baseline: 1.0767x; 1.0142x over previous
#include <cuda_runtime.h>
#include <cuda_bf16.h>
#include <math.h>
#include <stdint.h>

#define Bb 16
#define Dd 384
#define Nn_ 8192
#define Hh 512
#define SCALE 0.125f
#define EPSLN 1e-5f
#define NSPLIT 8

// ---------------- static scratch ----------------
__device__ __nv_bfloat16 g_xn[(long)Bb * Dd * Nn_];     // LN(x), bf16, [b][d][n]
__device__ __nv_bfloat16 g_kv[(long)Bb * 1024 * Nn_];   // rows 0..511 exp(k), 512..1023 v
__device__ float         g_ctxpart[(long)NSPLIT * 128 * 4096];
__device__ float         g_rowsum[Bb * 512];
__device__ __nv_bfloat16 g_T[(long)Bb * 384 * 512];
__device__ __nv_bfloat16 g_wf[(long)Bb * 384 * 384];
__device__ __nv_bfloat16 g_wqkv_bf[1536 * 384];

// ---------------- mma.sync helpers ----------------
__device__ __forceinline__ void ldsm_x4(unsigned addr, unsigned &r0, unsigned &r1,
                                        unsigned &r2, unsigned &r3) {
    asm volatile("ldmatrix.sync.aligned.m8n8.x4.shared.b16 {%0,%1,%2,%3}, [%4];\n"
                 : "=r"(r0), "=r"(r1), "=r"(r2), "=r"(r3) : "r"(addr));
}
__device__ __forceinline__ void ldsm_x4_t(unsigned addr, unsigned &r0, unsigned &r1,
                                          unsigned &r2, unsigned &r3) {
    asm volatile("ldmatrix.sync.aligned.m8n8.x4.trans.shared.b16 {%0,%1,%2,%3}, [%4];\n"
                 : "=r"(r0), "=r"(r1), "=r"(r2), "=r"(r3) : "r"(addr));
}
__device__ __forceinline__ void mma16816(float *c, const unsigned *a, unsigned b0, unsigned b1) {
    asm volatile("mma.sync.aligned.m16n8k16.row.col.f32.bf16.bf16.f32 "
                 "{%0,%1,%2,%3}, {%4,%5,%6,%7}, {%8,%9}, {%0,%1,%2,%3};\n"
                 : "+f"(c[0]), "+f"(c[1]), "+f"(c[2]), "+f"(c[3])
                 : "r"(a[0]), "r"(a[1]), "r"(a[2]), "r"(a[3]), "r"(b0), "r"(b1));
}
__device__ __forceinline__ void cpa16(uint32_t s, const void* g) {
    asm volatile("cp.async.cg.shared.global [%0], [%1], 16;" :: "r"(s), "l"(g));
}
__device__ __forceinline__ void cpa_commit() { asm volatile("cp.async.commit_group;" ::: "memory"); }
template<int NN>
__device__ __forceinline__ void cpa_wait() { asm volatile("cp.async.wait_group %0;" :: "n"(NN) : "memory"); }

#define ASTRIDE 40
#define BSTRIDE 136
#define A_ST_SZ (128 * ASTRIDE)
#define B_ST_SZ (32 * BSTRIDE)
#define GSMEM_BYTES ((4 * A_ST_SZ + 4 * B_ST_SZ) * 2)

// ================= 128x128 GEMM, 4 warps of 64x64, 4-stage cp.async =======
// Intra-chunk A-fragment pipelining (R13 champion inner loop).
// EPI 0: bf16 out; rows<512 exp() + rowsum atomics  (fused kv-GEMM)
// EPI 1: fp32 out + bias[row] + resid               (GEMM7)
template<int EPI>
__global__ __launch_bounds__(128, 2)
void gemm_w64(const __nv_bfloat16* __restrict__ A, const __nv_bfloat16* __restrict__ B,
              void* __restrict__ Cv, int K, int N,
              long sA, long sB, long sC,
              const float* __restrict__ bias, const float* __restrict__ resid, long sRes,
              float* __restrict__ rowsum) {
    extern __shared__ __nv_bfloat16 smem[];
    __nv_bfloat16* As = smem;
    __nv_bfloat16* Bs = smem + 4 * A_ST_SZ;

    int tid = threadIdx.x, lane = tid & 31, wid = tid >> 5;
    int bz = blockIdx.z;
    const __nv_bfloat16* Ab = A + (long)bz * sA;
    const __nv_bfloat16* Bp = B + (long)bz * sB;
    int bm0 = blockIdx.x * 128, bn0 = blockIdx.y * 128;

    uint32_t as_base = (uint32_t)__cvta_generic_to_shared(As);
    uint32_t bs_base = (uint32_t)__cvta_generic_to_shared(Bs);

    int nch = K / 32;
    auto load_stage = [&](int c, int buf) {
        int k0 = c * 32;
        #pragma unroll
        for (int i = 0; i < 4; i++) {          // A: 128 rows x 32 halves
            int v = i * 128 + tid;
            int row = v >> 2, kq = v & 3;
            cpa16(as_base + (uint32_t)(buf * A_ST_SZ + row * ASTRIDE + kq * 8) * 2,
                  Ab + (long)(bm0 + row) * K + k0 + kq * 8);
        }
        #pragma unroll
        for (int i = 0; i < 4; i++) {          // B: 32 rows x 128 halves
            int v = i * 128 + tid;
            int row = v >> 4, q = v & 15;
            cpa16(bs_base + (uint32_t)(buf * B_ST_SZ + row * BSTRIDE + q * 8) * 2,
                  Bp + (long)(k0 + row) * N + bn0 + q * 8);
        }
        cpa_commit();
    };

    int gid = lane >> 2, tid4 = lane & 3;
    int rsel = lane & 15, csel = (lane >> 4) * 8;
    int wm = (wid & 1) * 64, wn = (wid >> 1) * 64;

    float acc[4][8][4];
    #pragma unroll
    for (int i = 0; i < 4; i++)
        #pragma unroll
        for (int j = 0; j < 8; j++)
            #pragma unroll
            for (int k = 0; k < 4; k++) acc[i][j][k] = 0.f;

    load_stage(0, 0); load_stage(1, 1); load_stage(2, 2);

    #pragma unroll 1
    for (int c = 0; c < nch; c++) {
        int buf = c & 3;
        cpa_wait<2>();
        __syncthreads();
        if (c + 3 < nch) load_stage(c + 3, (c + 3) & 3);

        unsigned a0[4][4], a1[4][4], bf[4][4];
        #pragma unroll
        for (int mt = 0; mt < 4; mt++) {
            unsigned addr = as_base +
                (uint32_t)(buf * A_ST_SZ + (wm + mt * 16 + rsel) * ASTRIDE + csel) * 2;
            ldsm_x4(addr, a0[mt][0], a0[mt][1], a0[mt][2], a0[mt][3]);
        }
        #pragma unroll
        for (int nt2 = 0; nt2 < 4; nt2++) {
            unsigned addr = bs_base +
                (uint32_t)(buf * B_ST_SZ + rsel * BSTRIDE + wn + nt2 * 16 + csel) * 2;
            ldsm_x4_t(addr, bf[nt2][0], bf[nt2][1], bf[nt2][2], bf[nt2][3]);
        }
        #pragma unroll
        for (int mt = 0; mt < 4; mt++) {
            unsigned addr = as_base +
                (uint32_t)(buf * A_ST_SZ + (wm + mt * 16 + rsel) * ASTRIDE + 16 + csel) * 2;
            ldsm_x4(addr, a1[mt][0], a1[mt][1], a1[mt][2], a1[mt][3]);
        }
        #pragma unroll
        for (int mt = 0; mt < 4; mt++)
            #pragma unroll
            for (int nt = 0; nt < 8; nt++)
                mma16816(acc[mt][nt], a0[mt], bf[nt >> 1][(nt & 1) * 2],
                         bf[nt >> 1][(nt & 1) * 2 + 1]);
        #pragma unroll
        for (int nt2 = 0; nt2 < 4; nt2++) {
            unsigned addr = bs_base +
                (uint32_t)(buf * B_ST_SZ + (16 + rsel) * BSTRIDE + wn + nt2 * 16 + csel) * 2;
            ldsm_x4_t(addr, bf[nt2][0], bf[nt2][1], bf[nt2][2], bf[nt2][3]);
        }
        #pragma unroll
        for (int mt = 0; mt < 4; mt++)
            #pragma unroll
            for (int nt = 0; nt < 8; nt++)
                mma16816(acc[mt][nt], a1[mt], bf[nt >> 1][(nt & 1) * 2],
                         bf[nt >> 1][(nt & 1) * 2 + 1]);
        __syncthreads();
    }

    if (EPI == 0) {
        __nv_bfloat16* Cb = (__nv_bfloat16*)Cv + (long)bz * sC;
        bool isk = (bm0 < 512);
        float rs[8];
        #pragma unroll
        for (int i = 0; i < 8; i++) rs[i] = 0.f;
        #pragma unroll
        for (int mt = 0; mt < 4; mt++) {
            int row = bm0 + wm + mt * 16 + gid;
            #pragma unroll
            for (int nt = 0; nt < 8; nt++) {
                int col = bn0 + wn + nt * 8 + 2 * tid4;
                float c0 = acc[mt][nt][0], c1 = acc[mt][nt][1];
                float c2 = acc[mt][nt][2], c3 = acc[mt][nt][3];
                if (isk) {
                    c0 = __expf(c0); c1 = __expf(c1);
                    c2 = __expf(c2); c3 = __expf(c3);
                    rs[mt * 2] += c0 + c1;
                    rs[mt * 2 + 1] += c2 + c3;
                }
                *(__nv_bfloat162*)&Cb[(long)row * N + col] = __floats2bfloat162_rn(c0, c1);
                *(__nv_bfloat162*)&Cb[(long)(row + 8) * N + col] = __floats2bfloat162_rn(c2, c3);
            }
        }
        if (isk) {
            #pragma unroll
            for (int i = 0; i < 8; i++) {
                rs[i] += __shfl_xor_sync(0xffffffffu, rs[i], 1);
                rs[i] += __shfl_xor_sync(0xffffffffu, rs[i], 2);
            }
            if (tid4 == 0) {
                #pragma unroll
                for (int mt = 0; mt < 4; mt++) {
                    int row = bm0 + wm + mt * 16 + gid;
                    atomicAdd(&rowsum[bz * 512 + row], rs[mt * 2]);
                    atomicAdd(&rowsum[bz * 512 + row + 8], rs[mt * 2 + 1]);
                }
            }
        }
    } else {
        float* Cf = (float*)Cv + (long)bz * sC;
        const float* rp = resid + (long)bz * sRes;
        #pragma unroll
        for (int mt = 0; mt < 4; mt++) {
            int row = bm0 + wm + mt * 16 + gid;
            float b1 = bias[row], b2 = bias[row + 8];
            #pragma unroll
            for (int nt = 0; nt < 8; nt++) {
                int col = bn0 + wn + nt * 8 + 2 * tid4;
                float2 r1 = *(const float2*)&rp[(long)row * N + col];
                float2 r2 = *(const float2*)&rp[(long)(row + 8) * N + col];
                float2 o1 = make_float2(acc[mt][nt][0] + b1 + r1.x, acc[mt][nt][1] + b1 + r1.y);
                float2 o2 = make_float2(acc[mt][nt][2] + b2 + r2.x, acc[mt][nt][3] + b2 + r2.y);
                *(float2*)&Cf[(long)row * N + col] = o1;
                *(float2*)&Cf[(long)(row + 8) * N + col] = o2;
            }
        }
    }
}

// ================= R4 128x128 8-warp GEMM (GEMM6 only) =================
__global__ __launch_bounds__(256)
void gemm_small(const __nv_bfloat16* __restrict__ A, const __nv_bfloat16* __restrict__ B,
                __nv_bfloat16* __restrict__ C, int K, int N,
                long sA, long sB, long sC, float scale) {
    extern __shared__ __nv_bfloat16 smem[];
    __nv_bfloat16* As = smem;
    __nv_bfloat16* Bs = smem + 4 * A_ST_SZ;
    int tid = threadIdx.x, lane = tid & 31, wid = tid >> 5;
    int bz = blockIdx.z;
    const __nv_bfloat16* Ab = A + (long)bz * sA;
    const __nv_bfloat16* Bp = B + (long)bz * sB;
    int bm0 = blockIdx.x * 128, bn0 = blockIdx.y * 128;
    int am = tid >> 2, akq = tid & 3;
    int bk = tid >> 4, bnq = tid & 15;
    const __nv_bfloat16* Ag0 = Ab + (long)(bm0 + am) * K + akq * 8;
    const __nv_bfloat16* Ag1 = Ag0 + (long)64 * K;
    const __nv_bfloat16* Bg0 = Bp + (long)bk * N + bn0 + bnq * 8;
    const __nv_bfloat16* Bg1 = Bg0 + (long)16 * N;
    uint32_t a_s0 = (uint32_t)__cvta_generic_to_shared(&As[am * ASTRIDE + akq * 8]);
    uint32_t a_s1 = (uint32_t)__cvta_generic_to_shared(&As[(am + 64) * ASTRIDE + akq * 8]);
    uint32_t b_s0 = (uint32_t)__cvta_generic_to_shared(&Bs[bk * BSTRIDE + bnq * 8]);
    uint32_t b_s1 = (uint32_t)__cvta_generic_to_shared(&Bs[(bk + 16) * BSTRIDE + bnq * 8]);
    int nch = K / 32;
    auto load_stage = [&](int c, int buf) {
        int k0 = c * 32;
        cpa16(a_s0 + buf * A_ST_SZ * 2, Ag0 + k0);
        cpa16(a_s1 + buf * A_ST_SZ * 2, Ag1 + k0);
        cpa16(b_s0 + buf * B_ST_SZ * 2, Bg0 + (long)k0 * N);
        cpa16(b_s1 + buf * B_ST_SZ * 2, Bg1 + (long)k0 * N);
        cpa_commit();
    };
    int gid = lane >> 2, tid4 = lane & 3;
    int rsel = lane & 15, csel = (lane >> 4) * 8;
    int wm = (wid & 1) * 64, wn = (wid >> 1) * 32;
    uint32_t as_base = (uint32_t)__cvta_generic_to_shared(As);
    uint32_t bs_base = (uint32_t)__cvta_generic_to_shared(Bs);
    float acc[4][4][4];
    #pragma unroll
    for (int i = 0; i < 4; i++)
        #pragma unroll
        for (int j = 0; j < 4; j++)
            #pragma unroll
            for (int k = 0; k < 4; k++) acc[i][j][k] = 0.f;
    load_stage(0, 0); load_stage(1, 1); load_stage(2, 2);
    #pragma unroll 1
    for (int c = 0; c < nch; c++) {
        int buf = c & 3;
        cpa_wait<2>();
        __syncthreads();
        if (c + 3 < nch) load_stage(c + 3, (c + 3) & 3);
        #pragma unroll
        for (int ks = 0; ks < 32; ks += 16) {
            unsigned a[4][4], bf[2][4];
            #pragma unroll
            for (int mt = 0; mt < 4; mt++) {
                unsigned addr = as_base +
                    (buf * A_ST_SZ + (wm + mt * 16 + rsel) * ASTRIDE + ks + csel) * 2;
                ldsm_x4(addr, a[mt][0], a[mt][1], a[mt][2], a[mt][3]);
            }
            #pragma unroll
            for (int nt2 = 0; nt2 < 2; nt2++) {
                unsigned addr = bs_base +
                    (buf * B_ST_SZ + (ks + rsel) * BSTRIDE + wn + nt2 * 16 + csel) * 2;
                ldsm_x4_t(addr, bf[nt2][0], bf[nt2][1], bf[nt2][2], bf[nt2][3]);
            }
            #pragma unroll
            for (int mt = 0; mt < 4; mt++)
                #pragma unroll
                for (int nt = 0; nt < 4; nt++)
                    mma16816(acc[mt][nt], a[mt], bf[nt >> 1][(nt & 1) * 2],
                             bf[nt >> 1][(nt & 1) * 2 + 1]);
        }
        __syncthreads();
    }
    #pragma unroll
    for (int mt = 0; mt < 4; mt++) {
        int row = bm0 + wm + mt * 16 + gid;
        #pragma unroll
        for (int nt = 0; nt < 4; nt++) {
            int col = bn0 + wn + nt * 8 + 2 * tid4;
            __nv_bfloat16* Cb = C + (long)bz * sC;
            *(__nv_bfloat162*)&Cb[(long)row * N + col] =
                __floats2bfloat162_rn(acc[mt][nt][0] * scale, acc[mt][nt][1] * scale);
            *(__nv_bfloat162*)&Cb[(long)(row + 8) * N + col] =
                __floats2bfloat162_rn(acc[mt][nt][2] * scale, acc[mt][nt][3] * scale);
        }
    }
}

// ================= prep: weight convert + rowsum zero in one launch ======
__global__ void prep_kernel(const float* __restrict__ src, __nv_bfloat16* __restrict__ dst,
                            int n, float* __restrict__ zp, int nz) {
    int i = blockIdx.x * blockDim.x + threadIdx.x;
    if (i < n) dst[i] = __float2bfloat16(src[i]);
    if (i < nz) zp[i] = 0.f;
}

__global__ __launch_bounds__(256) void ln_norm_kernel(const float* __restrict__ x,
                                                      const float* __restrict__ gamma,
                                                      const float* __restrict__ beta,
                                                      __nv_bfloat16* __restrict__ xn) {
    __shared__ float gS[384], bS[384];
    __shared__ float red_s[8][33], red_q[8][33];
    __shared__ float mS[32], rS[32];
    int tid = threadIdx.x;
    int dg = tid >> 5, tn = tid & 31;
    int b = blockIdx.y;
    int n = blockIdx.x * 32 + tn;
    for (int i = tid; i < 384; i += 256) { gS[i] = gamma[i]; bS[i] = beta[i]; }
    const float* xp = x + (long)b * Dd * Nn_ + n;
    float v[48];
    float s = 0.f, q = 0.f;
    #pragma unroll
    for (int i = 0; i < 48; i++) {
        int d = dg + i * 8;
        v[i] = xp[(long)d * Nn_];
        s += v[i]; q += v[i] * v[i];
    }
    red_s[dg][tn] = s; red_q[dg][tn] = q;
    __syncthreads();
    if (dg == 0) {
        float ts = 0.f, tq = 0.f;
        #pragma unroll
        for (int j = 0; j < 8; j++) { ts += red_s[j][tn]; tq += red_q[j][tn]; }
        float mean = ts * (1.0f / Dd);
        float var = tq * (1.0f / Dd) - mean * mean;
        mS[tn] = mean; rS[tn] = rsqrtf(var + EPSLN);
    }
    __syncthreads();
    float mean = mS[tn], rstd = rS[tn];
    __nv_bfloat16* xo = xn + (long)b * Dd * Nn_ + n;
    #pragma unroll
    for (int i = 0; i < 48; i++) {
        int d = dg + i * 8;
        xo[(long)d * Nn_] = __float2bfloat16((v[i] - mean) * rstd * gS[d] + bS[d]);
    }
}

// ---------------- context via mma.sync (k already exp'd) ----------------
__global__ __launch_bounds__(256) void context_mma_kernel(const __nv_bfloat16* __restrict__ kv,
                                                          float* __restrict__ ctx_part) {
    __shared__ __align__(16) __nv_bfloat16 Ks[2][64 * 72];
    __shared__ __align__(16) __nv_bfloat16 Vs[2][64 * 72];
    const int LEN = Nn_ / NSPLIT;
    int sp = blockIdx.x, bh = blockIdx.y;
    int b = bh >> 3, h = bh & 7;
    const __nv_bfloat16* kb = kv + ((long)b * 1024 + h * 64) * Nn_;
    const __nv_bfloat16* vb = kv + ((long)b * 1024 + 512 + h * 64) * Nn_;
    int tid = threadIdx.x, lane = tid & 31, wid = tid >> 5;
    int lr = tid >> 3, lc = (tid & 7) * 8;
    int n0 = sp * LEN;
    int gid = lane >> 2, tid4 = lane & 3;
    int rsel = lane & 15, csel = (lane >> 4) * 8;
    int wm = (wid & 1) * 32, wn = (wid >> 1) * 16;
    float acc[2][2][4];
    #pragma unroll
    for (int i = 0; i < 2; i++)
        #pragma unroll
        for (int j = 0; j < 2; j++)
            #pragma unroll
            for (int k = 0; k < 4; k++) acc[i][j][k] = 0.f;
    uint4 k0v, k1v, v0v, v1v;
    const int NCH = LEN / 64;
    int so = lr * 72 + lc;
    k0v = *(const uint4*)(kb + (long)lr * Nn_ + n0 + lc);
    k1v = *(const uint4*)(kb + (long)(lr + 32) * Nn_ + n0 + lc);
    v0v = *(const uint4*)(vb + (long)lr * Nn_ + n0 + lc);
    v1v = *(const uint4*)(vb + (long)(lr + 32) * Nn_ + n0 + lc);
    *(uint4*)&Ks[0][so] = k0v; *(uint4*)&Ks[0][so + 32 * 72] = k1v;
    *(uint4*)&Vs[0][so] = v0v; *(uint4*)&Vs[0][so + 32 * 72] = v1v;
    __syncthreads();
    for (int c = 0; c < NCH; c++) {
        int buf = c & 1;
        if (c + 1 < NCH) {
            int off = n0 + (c + 1) * 64 + lc;
            k0v = *(const uint4*)(kb + (long)lr * Nn_ + off);
            k1v = *(const uint4*)(kb + (long)(lr + 32) * Nn_ + off);
            v0v = *(const uint4*)(vb + (long)lr * Nn_ + off);
            v1v = *(const uint4*)(vb + (long)(lr + 32) * Nn_ + off);
        }
        #pragma unroll
        for (int ks = 0; ks < 64; ks += 16) {
            unsigned a[2][4], bf[4];
            #pragma unroll
            for (int mt = 0; mt < 2; mt++) {
                unsigned addr = (unsigned)__cvta_generic_to_shared(
                    &Ks[buf][(wm + mt * 16 + rsel) * 72 + ks + csel]);
                ldsm_x4(addr, a[mt][0], a[mt][1], a[mt][2], a[mt][3]);
            }
            {
                unsigned addr = (unsigned)__cvta_generic_to_shared(
                    &Vs[buf][(wn + rsel) * 72 + ks + csel]);
                ldsm_x4(addr, bf[0], bf[1], bf[2], bf[3]);
            }
            #pragma unroll
            for (int mt = 0; mt < 2; mt++)
                #pragma unroll
                for (int nt = 0; nt < 2; nt++)
                    mma16816(acc[mt][nt], a[mt], bf[nt], bf[nt + 2]);
        }
        if (c + 1 < NCH) {
            int nb = (c + 1) & 1;
            *(uint4*)&Ks[nb][so] = k0v; *(uint4*)&Ks[nb][so + 32 * 72] = k1v;
            *(uint4*)&Vs[nb][so] = v0v; *(uint4*)&Vs[nb][so + 32 * 72] = v1v;
        }
        __syncthreads();
    }
    float* cp = ctx_part + ((long)sp * 128 + bh) * 4096;
    #pragma unroll
    for (int mt = 0; mt < 2; mt++) {
        int row = wm + mt * 16 + gid;
        #pragma unroll
        for (int nt = 0; nt < 2; nt++) {
            int col = wn + nt * 8 + 2 * tid4;
            *(float2*)&cp[row * 64 + col] = make_float2(acc[mt][nt][0], acc[mt][nt][1]);
            *(float2*)&cp[(row + 8) * 64 + col] = make_float2(acc[mt][nt][2], acc[mt][nt][3]);
        }
    }
}

// ------------- T build -------------
__global__ __launch_bounds__(256) void build_T_kernel(const float* __restrict__ ctx_part,
                                                      const float* __restrict__ rowsum,
                                                      const float* __restrict__ wout,
                                                      __nv_bfloat16* __restrict__ T) {
    int bh = blockIdx.x;
    int b = bh >> 3, h = bh & 7;
    __shared__ float ctxS[64][65];
    __shared__ float wS[64][65];
    int tid = threadIdx.x;
    #pragma unroll
    for (int i = 0; i < 16; i++) {
        int idx = tid + i * 256;
        int d = idx >> 6;
        float s = 0.f;
        #pragma unroll
        for (int sp = 0; sp < NSPLIT; sp++)
            s += ctx_part[((long)sp * 128 + bh) * 4096 + idx];
        ctxS[d][idx & 63] = s / rowsum[b * 512 + h * 64 + d];
    }
    __syncthreads();
    __nv_bfloat16* Tb = T + (long)b * 384 * 512;
    for (int c = 0; c < 6; c++) {
        #pragma unroll
        for (int i = 0; i < 16; i++) {
            int idx = tid + i * 256;
            int dr = idx >> 6, e = idx & 63;
            wS[dr][e] = wout[(long)(c * 64 + dr) * Hh + h * 64 + e];
        }
        __syncthreads();
        #pragma unroll
        for (int i = 0; i < 16; i++) {
            int idx = tid + i * 256;
            int dl = idx >> 6, dd = idx & 63;
            float s = 0.f;
            #pragma unroll
            for (int e = 0; e < 64; e++)
                s += wS[dl][e] * ctxS[dd][e];
            Tb[(long)(c * 64 + dl) * 512 + h * 64 + dd] = __float2bfloat16(s);
        }
        __syncthreads();
    }
}

// -------------------------------------------------------------------------
extern "C" void kernel_launch(void* const* d_in, const int* in_sizes, int n_in,
                              void* d_out, int out_size) {
    (void)in_sizes; (void)n_in; (void)out_size;
    const float* x     = (const float*)d_in[0];
    const float* gam   = (const float*)d_in[1];
    const float* bet   = (const float*)d_in[2];
    const float* w_qkv = (const float*)d_in[3];
    const float* w_out = (const float*)d_in[4];
    const float* b_out = (const float*)d_in[5];
    float* out = (float*)d_out;

    __nv_bfloat16 *p_xn, *p_kv, *p_T, *p_wf, *p_wq;
    float *p_ctxp, *p_rowsum;
    cudaGetSymbolAddress((void**)&p_xn,     g_xn);
    cudaGetSymbolAddress((void**)&p_kv,     g_kv);
    cudaGetSymbolAddress((void**)&p_ctxp,   g_ctxpart);
    cudaGetSymbolAddress((void**)&p_rowsum, g_rowsum);
    cudaGetSymbolAddress((void**)&p_T,      g_T);
    cudaGetSymbolAddress((void**)&p_wf,     g_wf);
    cudaGetSymbolAddress((void**)&p_wq,     g_wqkv_bf);

    cudaFuncSetAttribute(gemm_w64<0>, cudaFuncAttributeMaxDynamicSharedMemorySize, GSMEM_BYTES);
    cudaFuncSetAttribute(gemm_w64<1>, cudaFuncAttributeMaxDynamicSharedMemorySize, GSMEM_BYTES);
    cudaFuncSetAttribute(gemm_small, cudaFuncAttributeMaxDynamicSharedMemorySize, GSMEM_BYTES);

    // 0. prep (weight cvt + rowsum zero, one launch)
    prep_kernel<<<(1536 * 384 + 255) / 256, 256>>>(w_qkv, p_wq, 1536 * 384,
                                                   p_rowsum, Bb * 512);

    // 1. LN -> bf16 x_norm
    ln_norm_kernel<<<dim3(Nn_ / 32, Bb), 256>>>(x, gam, bet, p_xn);

    // 2. kv = W_kv @ xn (M=1024, one launch); k rows exp'd + rowsum atomics
    gemm_w64<0><<<dim3(8, 64, Bb), 128, GSMEM_BYTES>>>(
        p_wq + (long)512 * Dd, p_xn, p_kv, Dd, Nn_,
        0L, (long)Dd * Nn_, (long)1024 * Nn_,
        nullptr, nullptr, 0L, p_rowsum);

    // 3. partial contexts (NSPLIT=8)
    context_mma_kernel<<<dim3(NSPLIT, 128), 256>>>(p_kv, p_ctxp);

    // 4. T
    build_T_kernel<<<128, 256>>>(p_ctxp, p_rowsum, w_out, p_T);

    // 5. W_final[b] = SCALE * T[b] @ W_q
    gemm_small<<<dim3(3, 3, Bb), 256, GSMEM_BYTES>>>(
        p_T, p_wq, p_wf, 512, 384,
        (long)384 * 512, 0L, (long)384 * 384, SCALE);

    // 6. out = W_final[b] @ xn + b_out + x
    gemm_w64<1><<<dim3(3, 64, Bb), 128, GSMEM_BYTES>>>(
        p_wf, p_xn, out, Dd, Nn_,
        (long)384 * 384, (long)Dd * Nn_, (long)Dd * Nn_,
        b_out, x, (long)Dd * Nn_, nullptr);
}

// round 16
// speedup vs baseline: 1.0769x; 1.0002x over previous
#include <cuda_runtime.h>
#include <cuda_bf16.h>
#include <math.h>
#include <stdint.h>

#define Bb 16
#define Dd 384
#define Nn_ 8192
#define Hh 512
#define SCALE 0.125f
#define EPSLN 1e-5f
#define NSPLIT 8

// ---------------- static scratch ----------------
__device__ __nv_bfloat16 g_xn[(long)Bb * Dd * Nn_];     // LN(x), bf16, [b][d][n]
__device__ __nv_bfloat16 g_kv[(long)Bb * 1024 * Nn_];   // rows 0..511 exp(k), 512..1023 v
__device__ float         g_ctxpart[(long)NSPLIT * 128 * 4096];
__device__ float         g_rowsum[Bb * 512];
__device__ __nv_bfloat16 g_T[(long)Bb * 384 * 512];
__device__ __nv_bfloat16 g_wf[(long)Bb * 384 * 384];
__device__ __nv_bfloat16 g_wqkv_bf[1536 * 384];

// ---------------- mma.sync helpers ----------------
__device__ __forceinline__ void ldsm_x4(unsigned addr, unsigned &r0, unsigned &r1,
                                        unsigned &r2, unsigned &r3) {
    asm volatile("ldmatrix.sync.aligned.m8n8.x4.shared.b16 {%0,%1,%2,%3}, [%4];\n"
                 : "=r"(r0), "=r"(r1), "=r"(r2), "=r"(r3) : "r"(addr));
}
__device__ __forceinline__ void ldsm_x4_t(unsigned addr, unsigned &r0, unsigned &r1,
                                          unsigned &r2, unsigned &r3) {
    asm volatile("ldmatrix.sync.aligned.m8n8.x4.trans.shared.b16 {%0,%1,%2,%3}, [%4];\n"
                 : "=r"(r0), "=r"(r1), "=r"(r2), "=r"(r3) : "r"(addr));
}
__device__ __forceinline__ void mma16816(float *c, const unsigned *a, unsigned b0, unsigned b1) {
    asm volatile("mma.sync.aligned.m16n8k16.row.col.f32.bf16.bf16.f32 "
                 "{%0,%1,%2,%3}, {%4,%5,%6,%7}, {%8,%9}, {%0,%1,%2,%3};\n"
                 : "+f"(c[0]), "+f"(c[1]), "+f"(c[2]), "+f"(c[3])
                 : "r"(a[0]), "r"(a[1]), "r"(a[2]), "r"(a[3]), "r"(b0), "r"(b1));
}
__device__ __forceinline__ void cpa16(uint32_t s, const void* g) {
    asm volatile("cp.async.cg.shared.global [%0], [%1], 16;" :: "r"(s), "l"(g));
}
__device__ __forceinline__ void cpa_commit() { asm volatile("cp.async.commit_group;" ::: "memory"); }
template<int NN>
__device__ __forceinline__ void cpa_wait() { asm volatile("cp.async.wait_group %0;" :: "n"(NN) : "memory"); }

#define ASTRIDE 40
#define BSTRIDE 136
#define A_ST_SZ (128 * ASTRIDE)
#define B_ST_SZ (32 * BSTRIDE)
#define GSMEM_BYTES ((4 * A_ST_SZ + 4 * B_ST_SZ) * 2)

// ================= 128x128 GEMM, 4 warps of 64x64, 4-stage cp.async =======
// Intra-chunk A-fragment pipelining (champion inner loop).
// EPI 0: bf16 out; rows<512 exp() + rowsum atomics  (fused kv-GEMM)
// EPI 1: fp32 out + bias[row] + resid               (GEMM7)
template<int EPI>
__global__ __launch_bounds__(128, 2)
void gemm_w64(const __nv_bfloat16* __restrict__ A, const __nv_bfloat16* __restrict__ B,
              void* __restrict__ Cv, int K, int N,
              long sA, long sB, long sC,
              const float* __restrict__ bias, const float* __restrict__ resid, long sRes,
              float* __restrict__ rowsum) {
    extern __shared__ __nv_bfloat16 smem[];
    __nv_bfloat16* As = smem;
    __nv_bfloat16* Bs = smem + 4 * A_ST_SZ;

    int tid = threadIdx.x, lane = tid & 31, wid = tid >> 5;
    int bz = blockIdx.z;
    const __nv_bfloat16* Ab = A + (long)bz * sA;
    const __nv_bfloat16* Bp = B + (long)bz * sB;
    int bm0 = blockIdx.x * 128, bn0 = blockIdx.y * 128;

    uint32_t as_base = (uint32_t)__cvta_generic_to_shared(As);
    uint32_t bs_base = (uint32_t)__cvta_generic_to_shared(Bs);

    int nch = K / 32;
    auto load_stage = [&](int c, int buf) {
        int k0 = c * 32;
        #pragma unroll
        for (int i = 0; i < 4; i++) {          // A: 128 rows x 32 halves
            int v = i * 128 + tid;
            int row = v >> 2, kq = v & 3;
            cpa16(as_base + (uint32_t)(buf * A_ST_SZ + row * ASTRIDE + kq * 8) * 2,
                  Ab + (long)(bm0 + row) * K + k0 + kq * 8);
        }
        #pragma unroll
        for (int i = 0; i < 4; i++) {          // B: 32 rows x 128 halves
            int v = i * 128 + tid;
            int row = v >> 4, q = v & 15;
            cpa16(bs_base + (uint32_t)(buf * B_ST_SZ + row * BSTRIDE + q * 8) * 2,
                  Bp + (long)(k0 + row) * N + bn0 + q * 8);
        }
        cpa_commit();
    };

    int gid = lane >> 2, tid4 = lane & 3;
    int rsel = lane & 15, csel = (lane >> 4) * 8;
    int wm = (wid & 1) * 64, wn = (wid >> 1) * 64;

    float acc[4][8][4];
    #pragma unroll
    for (int i = 0; i < 4; i++)
        #pragma unroll
        for (int j = 0; j < 8; j++)
            #pragma unroll
            for (int k = 0; k < 4; k++) acc[i][j][k] = 0.f;

    load_stage(0, 0); load_stage(1, 1); load_stage(2, 2);

    #pragma unroll 1
    for (int c = 0; c < nch; c++) {
        int buf = c & 3;
        cpa_wait<2>();
        __syncthreads();
        if (c + 3 < nch) load_stage(c + 3, (c + 3) & 3);

        unsigned a0[4][4], a1[4][4], bf[4][4];
        #pragma unroll
        for (int mt = 0; mt < 4; mt++) {
            unsigned addr = as_base +
                (uint32_t)(buf * A_ST_SZ + (wm + mt * 16 + rsel) * ASTRIDE + csel) * 2;
            ldsm_x4(addr, a0[mt][0], a0[mt][1], a0[mt][2], a0[mt][3]);
        }
        #pragma unroll
        for (int nt2 = 0; nt2 < 4; nt2++) {
            unsigned addr = bs_base +
                (uint32_t)(buf * B_ST_SZ + rsel * BSTRIDE + wn + nt2 * 16 + csel) * 2;
            ldsm_x4_t(addr, bf[nt2][0], bf[nt2][1], bf[nt2][2], bf[nt2][3]);
        }
        #pragma unroll
        for (int mt = 0; mt < 4; mt++) {
            unsigned addr = as_base +
                (uint32_t)(buf * A_ST_SZ + (wm + mt * 16 + rsel) * ASTRIDE + 16 + csel) * 2;
            ldsm_x4(addr, a1[mt][0], a1[mt][1], a1[mt][2], a1[mt][3]);
        }
        #pragma unroll
        for (int mt = 0; mt < 4; mt++)
            #pragma unroll
            for (int nt = 0; nt < 8; nt++)
                mma16816(acc[mt][nt], a0[mt], bf[nt >> 1][(nt & 1) * 2],
                         bf[nt >> 1][(nt & 1) * 2 + 1]);
        #pragma unroll
        for (int nt2 = 0; nt2 < 4; nt2++) {
            unsigned addr = bs_base +
                (uint32_t)(buf * B_ST_SZ + (16 + rsel) * BSTRIDE + wn + nt2 * 16 + csel) * 2;
            ldsm_x4_t(addr, bf[nt2][0], bf[nt2][1], bf[nt2][2], bf[nt2][3]);
        }
        #pragma unroll
        for (int mt = 0; mt < 4; mt++)
            #pragma unroll
            for (int nt = 0; nt < 8; nt++)
                mma16816(acc[mt][nt], a1[mt], bf[nt >> 1][(nt & 1) * 2],
                         bf[nt >> 1][(nt & 1) * 2 + 1]);
        __syncthreads();
    }

    if (EPI == 0) {
        __nv_bfloat16* Cb = (__nv_bfloat16*)Cv + (long)bz * sC;
        bool isk = (bm0 < 512);
        float rs[8];
        #pragma unroll
        for (int i = 0; i < 8; i++) rs[i] = 0.f;
        #pragma unroll
        for (int mt = 0; mt < 4; mt++) {
            int row = bm0 + wm + mt * 16 + gid;
            #pragma unroll
            for (int nt = 0; nt < 8; nt++) {
                int col = bn0 + wn + nt * 8 + 2 * tid4;
                float c0 = acc[mt][nt][0], c1 = acc[mt][nt][1];
                float c2 = acc[mt][nt][2], c3 = acc[mt][nt][3];
                if (isk) {
                    c0 = __expf(c0); c1 = __expf(c1);
                    c2 = __expf(c2); c3 = __expf(c3);
                    rs[mt * 2] += c0 + c1;
                    rs[mt * 2 + 1] += c2 + c3;
                }
                *(__nv_bfloat162*)&Cb[(long)row * N + col] = __floats2bfloat162_rn(c0, c1);
                *(__nv_bfloat162*)&Cb[(long)(row + 8) * N + col] = __floats2bfloat162_rn(c2, c3);
            }
        }
        if (isk) {
            #pragma unroll
            for (int i = 0; i < 8; i++) {
                rs[i] += __shfl_xor_sync(0xffffffffu, rs[i], 1);
                rs[i] += __shfl_xor_sync(0xffffffffu, rs[i], 2);
            }
            if (tid4 == 0) {
                #pragma unroll
                for (int mt = 0; mt < 4; mt++) {
                    int row = bm0 + wm + mt * 16 + gid;
                    atomicAdd(&rowsum[bz * 512 + row], rs[mt * 2]);
                    atomicAdd(&rowsum[bz * 512 + row + 8], rs[mt * 2 + 1]);
                }
            }
        }
    } else {
        float* Cf = (float*)Cv + (long)bz * sC;
        const float* rp = resid + (long)bz * sRes;
        #pragma unroll
        for (int mt = 0; mt < 4; mt++) {
            int row = bm0 + wm + mt * 16 + gid;
            float b1 = bias[row], b2 = bias[row + 8];
            #pragma unroll
            for (int nt = 0; nt < 8; nt++) {
                int col = bn0 + wn + nt * 8 + 2 * tid4;
                float2 r1 = *(const float2*)&rp[(long)row * N + col];
                float2 r2 = *(const float2*)&rp[(long)(row + 8) * N + col];
                float2 o1 = make_float2(acc[mt][nt][0] + b1 + r1.x, acc[mt][nt][1] + b1 + r1.y);
                float2 o2 = make_float2(acc[mt][nt][2] + b2 + r2.x, acc[mt][nt][3] + b2 + r2.y);
                *(float2*)&Cf[(long)row * N + col] = o1;
                *(float2*)&Cf[(long)(row + 8) * N + col] = o2;
            }
        }
    }
}

// ================= R4 128x128 8-warp GEMM (GEMM6 only) =================
__global__ __launch_bounds__(256)
void gemm_small(const __nv_bfloat16* __restrict__ A, const __nv_bfloat16* __restrict__ B,
                __nv_bfloat16* __restrict__ C, int K, int N,
                long sA, long sB, long sC, float scale) {
    extern __shared__ __nv_bfloat16 smem[];
    __nv_bfloat16* As = smem;
    __nv_bfloat16* Bs = smem + 4 * A_ST_SZ;
    int tid = threadIdx.x, lane = tid & 31, wid = tid >> 5;
    int bz = blockIdx.z;
    const __nv_bfloat16* Ab = A + (long)bz * sA;
    const __nv_bfloat16* Bp = B + (long)bz * sB;
    int bm0 = blockIdx.x * 128, bn0 = blockIdx.y * 128;
    int am = tid >> 2, akq = tid & 3;
    int bk = tid >> 4, bnq = tid & 15;
    const __nv_bfloat16* Ag0 = Ab + (long)(bm0 + am) * K + akq * 8;
    const __nv_bfloat16* Ag1 = Ag0 + (long)64 * K;
    const __nv_bfloat16* Bg0 = Bp + (long)bk * N + bn0 + bnq * 8;
    const __nv_bfloat16* Bg1 = Bg0 + (long)16 * N;
    uint32_t a_s0 = (uint32_t)__cvta_generic_to_shared(&As[am * ASTRIDE + akq * 8]);
    uint32_t a_s1 = (uint32_t)__cvta_generic_to_shared(&As[(am + 64) * ASTRIDE + akq * 8]);
    uint32_t b_s0 = (uint32_t)__cvta_generic_to_shared(&Bs[bk * BSTRIDE + bnq * 8]);
    uint32_t b_s1 = (uint32_t)__cvta_generic_to_shared(&Bs[(bk + 16) * BSTRIDE + bnq * 8]);
    int nch = K / 32;
    auto load_stage = [&](int c, int buf) {
        int k0 = c * 32;
        cpa16(a_s0 + buf * A_ST_SZ * 2, Ag0 + k0);
        cpa16(a_s1 + buf * A_ST_SZ * 2, Ag1 + k0);
        cpa16(b_s0 + buf * B_ST_SZ * 2, Bg0 + (long)k0 * N);
        cpa16(b_s1 + buf * B_ST_SZ * 2, Bg1 + (long)k0 * N);
        cpa_commit();
    };
    int gid = lane >> 2, tid4 = lane & 3;
    int rsel = lane & 15, csel = (lane >> 4) * 8;
    int wm = (wid & 1) * 64, wn = (wid >> 1) * 32;
    uint32_t as_base = (uint32_t)__cvta_generic_to_shared(As);
    uint32_t bs_base = (uint32_t)__cvta_generic_to_shared(Bs);
    float acc[4][4][4];
    #pragma unroll
    for (int i = 0; i < 4; i++)
        #pragma unroll
        for (int j = 0; j < 4; j++)
            #pragma unroll
            for (int k = 0; k < 4; k++) acc[i][j][k] = 0.f;
    load_stage(0, 0); load_stage(1, 1); load_stage(2, 2);
    #pragma unroll 1
    for (int c = 0; c < nch; c++) {
        int buf = c & 3;
        cpa_wait<2>();
        __syncthreads();
        if (c + 3 < nch) load_stage(c + 3, (c + 3) & 3);
        #pragma unroll
        for (int ks = 0; ks < 32; ks += 16) {
            unsigned a[4][4], bf[2][4];
            #pragma unroll
            for (int mt = 0; mt < 4; mt++) {
                unsigned addr = as_base +
                    (buf * A_ST_SZ + (wm + mt * 16 + rsel) * ASTRIDE + ks + csel) * 2;
                ldsm_x4(addr, a[mt][0], a[mt][1], a[mt][2], a[mt][3]);
            }
            #pragma unroll
            for (int nt2 = 0; nt2 < 2; nt2++) {
                unsigned addr = bs_base +
                    (buf * B_ST_SZ + (ks + rsel) * BSTRIDE + wn + nt2 * 16 + csel) * 2;
                ldsm_x4_t(addr, bf[nt2][0], bf[nt2][1], bf[nt2][2], bf[nt2][3]);
            }
            #pragma unroll
            for (int mt = 0; mt < 4; mt++)
                #pragma unroll
                for (int nt = 0; nt < 4; nt++)
                    mma16816(acc[mt][nt], a[mt], bf[nt >> 1][(nt & 1) * 2],
                             bf[nt >> 1][(nt & 1) * 2 + 1]);
        }
        __syncthreads();
    }
    #pragma unroll
    for (int mt = 0; mt < 4; mt++) {
        int row = bm0 + wm + mt * 16 + gid;
        #pragma unroll
        for (int nt = 0; nt < 4; nt++) {
            int col = bn0 + wn + nt * 8 + 2 * tid4;
            __nv_bfloat16* Cb = C + (long)bz * sC;
            *(__nv_bfloat162*)&Cb[(long)row * N + col] =
                __floats2bfloat162_rn(acc[mt][nt][0] * scale, acc[mt][nt][1] * scale);
            *(__nv_bfloat162*)&Cb[(long)(row + 8) * N + col] =
                __floats2bfloat162_rn(acc[mt][nt][2] * scale, acc[mt][nt][3] * scale);
        }
    }
}

// ================= prep: weight convert + rowsum zero in one launch ======
__global__ void prep_kernel(const float* __restrict__ src, __nv_bfloat16* __restrict__ dst,
                            int n, float* __restrict__ zp, int nz) {
    int i = blockIdx.x * blockDim.x + threadIdx.x;
    if (i < n) dst[i] = __float2bfloat16(src[i]);
    if (i < nz) zp[i] = 0.f;
}

__global__ __launch_bounds__(256) void ln_norm_kernel(const float* __restrict__ x,
                                                      const float* __restrict__ gamma,
                                                      const float* __restrict__ beta,
                                                      __nv_bfloat16* __restrict__ xn) {
    __shared__ float gS[384], bS[384];
    __shared__ float red_s[8][33], red_q[8][33];
    __shared__ float mS[32], rS[32];
    int tid = threadIdx.x;
    int dg = tid >> 5, tn = tid & 31;
    int b = blockIdx.y;
    int n = blockIdx.x * 32 + tn;
    for (int i = tid; i < 384; i += 256) { gS[i] = gamma[i]; bS[i] = beta[i]; }
    const float* xp = x + (long)b * Dd * Nn_ + n;
    float v[48];
    float s = 0.f, q = 0.f;
    #pragma unroll
    for (int i = 0; i < 48; i++) {
        int d = dg + i * 8;
        v[i] = xp[(long)d * Nn_];
        s += v[i]; q += v[i] * v[i];
    }
    red_s[dg][tn] = s; red_q[dg][tn] = q;
    __syncthreads();
    if (dg == 0) {
        float ts = 0.f, tq = 0.f;
        #pragma unroll
        for (int j = 0; j < 8; j++) { ts += red_s[j][tn]; tq += red_q[j][tn]; }
        float mean = ts * (1.0f / Dd);
        float var = tq * (1.0f / Dd) - mean * mean;
        mS[tn] = mean; rS[tn] = rsqrtf(var + EPSLN);
    }
    __syncthreads();
    float mean = mS[tn], rstd = rS[tn];
    __nv_bfloat16* xo = xn + (long)b * Dd * Nn_ + n;
    #pragma unroll
    for (int i = 0; i < 48; i++) {
        int d = dg + i * 8;
        xo[(long)d * Nn_] = __float2bfloat16((v[i] - mean) * rstd * gS[d] + bS[d]);
    }
}

// -------- context via mma.sync, 3-stage cp.async (k already exp'd) --------
#define CSTR 72
#define C_TSZ (64 * CSTR)                       // elems per 64x64 tile (padded)
#define CTX_SMEM (6 * C_TSZ * 2)                // 3 stages x (K+V) = 55296 B

__global__ __launch_bounds__(256)
void context_mma_kernel(const __nv_bfloat16* __restrict__ kv,
                        float* __restrict__ ctx_part) {
    extern __shared__ __nv_bfloat16 csm[];
    const int LEN = Nn_ / NSPLIT;               // 1024
    int sp = blockIdx.x, bh = blockIdx.y;
    int b = bh >> 3, h = bh & 7;
    const __nv_bfloat16* kb = kv + ((long)b * 1024 + h * 64) * Nn_;
    const __nv_bfloat16* vb = kv + ((long)b * 1024 + 512 + h * 64) * Nn_;
    int tid = threadIdx.x, lane = tid & 31, wid = tid >> 5;
    int n0 = sp * LEN;
    int gid = lane >> 2, tid4 = lane & 3;
    int rsel = lane & 15, csel = (lane >> 4) * 8;
    int wm = (wid & 1) * 32, wn = (wid >> 1) * 16;

    uint32_t ks_base = (uint32_t)__cvta_generic_to_shared(csm);
    uint32_t vs_base = ks_base + 3 * C_TSZ * 2;

    const int NCH = LEN / 64;                   // 16
    auto cload = [&](int c, int buf) {
        int n0c = n0 + c * 64;
        #pragma unroll
        for (int i = 0; i < 2; i++) {           // 512 16B chunks each for K and V
            int v = i * 256 + tid;
            int row = v >> 3, q = v & 7;
            cpa16(ks_base + (uint32_t)(buf * C_TSZ + row * CSTR + q * 8) * 2,
                  kb + (long)row * Nn_ + n0c + q * 8);
            cpa16(vs_base + (uint32_t)(buf * C_TSZ + row * CSTR + q * 8) * 2,
                  vb + (long)row * Nn_ + n0c + q * 8);
        }
        cpa_commit();
    };

    float acc[2][2][4];
    #pragma unroll
    for (int i = 0; i < 2; i++)
        #pragma unroll
        for (int j = 0; j < 2; j++)
            #pragma unroll
            for (int k = 0; k < 4; k++) acc[i][j][k] = 0.f;

    cload(0, 0); cload(1, 1);

    #pragma unroll 1
    for (int c = 0; c < NCH; c++) {
        int buf = c % 3;
        cpa_wait<1>();
        __syncthreads();
        if (c + 2 < NCH) cload(c + 2, (c + 2) % 3);
        #pragma unroll
        for (int ks = 0; ks < 64; ks += 16) {
            unsigned a[2][4], bf[4];
            #pragma unroll
            for (int mt = 0; mt < 2; mt++) {
                unsigned addr = ks_base +
                    (uint32_t)(buf * C_TSZ + (wm + mt * 16 + rsel) * CSTR + ks + csel) * 2;
                ldsm_x4(addr, a[mt][0], a[mt][1], a[mt][2], a[mt][3]);
            }
            {
                unsigned addr = vs_base +
                    (uint32_t)(buf * C_TSZ + (wn + rsel) * CSTR + ks + csel) * 2;
                ldsm_x4(addr, bf[0], bf[1], bf[2], bf[3]);
            }
            #pragma unroll
            for (int mt = 0; mt < 2; mt++)
                #pragma unroll
                for (int nt = 0; nt < 2; nt++)
                    mma16816(acc[mt][nt], a[mt], bf[nt], bf[nt + 2]);
        }
    }

    float* cp = ctx_part + ((long)sp * 128 + bh) * 4096;
    #pragma unroll
    for (int mt = 0; mt < 2; mt++) {
        int row = wm + mt * 16 + gid;
        #pragma unroll
        for (int nt = 0; nt < 2; nt++) {
            int col = wn + nt * 8 + 2 * tid4;
            *(float2*)&cp[row * 64 + col] = make_float2(acc[mt][nt][0], acc[mt][nt][1]);
            *(float2*)&cp[(row + 8) * 64 + col] = make_float2(acc[mt][nt][2], acc[mt][nt][3]);
        }
    }
}

// ------------- T build -------------
__global__ __launch_bounds__(256) void build_T_kernel(const float* __restrict__ ctx_part,
                                                      const float* __restrict__ rowsum,
                                                      const float* __restrict__ wout,
                                                      __nv_bfloat16* __restrict__ T) {
    int bh = blockIdx.x;
    int b = bh >> 3, h = bh & 7;
    __shared__ float ctxS[64][65];
    __shared__ float wS[64][65];
    int tid = threadIdx.x;
    #pragma unroll
    for (int i = 0; i < 16; i++) {
        int idx = tid + i * 256;
        int d = idx >> 6;
        float s = 0.f;
        #pragma unroll
        for (int sp = 0; sp < NSPLIT; sp++)
            s += ctx_part[((long)sp * 128 + bh) * 4096 + idx];
        ctxS[d][idx & 63] = s / rowsum[b * 512 + h * 64 + d];
    }
    __syncthreads();
    __nv_bfloat16* Tb = T + (long)b * 384 * 512;
    for (int c = 0; c < 6; c++) {
        #pragma unroll
        for (int i = 0; i < 16; i++) {
            int idx = tid + i * 256;
            int dr = idx >> 6, e = idx & 63;
            wS[dr][e] = wout[(long)(c * 64 + dr) * Hh + h * 64 + e];
        }
        __syncthreads();
        #pragma unroll
        for (int i = 0; i < 16; i++) {
            int idx = tid + i * 256;
            int dl = idx >> 6, dd = idx & 63;
            float s = 0.f;
            #pragma unroll
            for (int e = 0; e < 64; e++)
                s += wS[dl][e] * ctxS[dd][e];
            Tb[(long)(c * 64 + dl) * 512 + h * 64 + dd] = __float2bfloat16(s);
        }
        __syncthreads();
    }
}

// -------------------------------------------------------------------------
extern "C" void kernel_launch(void* const* d_in, const int* in_sizes, int n_in,
                              void* d_out, int out_size) {
    (void)in_sizes; (void)n_in; (void)out_size;
    const float* x     = (const float*)d_in[0];
    const float* gam   = (const float*)d_in[1];
    const float* bet   = (const float*)d_in[2];
    const float* w_qkv = (const float*)d_in[3];
    const float* w_out = (const float*)d_in[4];
    const float* b_out = (const float*)d_in[5];
    float* out = (float*)d_out;

    __nv_bfloat16 *p_xn, *p_kv, *p_T, *p_wf, *p_wq;
    float *p_ctxp, *p_rowsum;
    cudaGetSymbolAddress((void**)&p_xn,     g_xn);
    cudaGetSymbolAddress((void**)&p_kv,     g_kv);
    cudaGetSymbolAddress((void**)&p_ctxp,   g_ctxpart);
    cudaGetSymbolAddress((void**)&p_rowsum, g_rowsum);
    cudaGetSymbolAddress((void**)&p_T,      g_T);
    cudaGetSymbolAddress((void**)&p_wf,     g_wf);
    cudaGetSymbolAddress((void**)&p_wq,     g_wqkv_bf);

    cudaFuncSetAttribute(gemm_w64<0>, cudaFuncAttributeMaxDynamicSharedMemorySize, GSMEM_BYTES);
    cudaFuncSetAttribute(gemm_w64<1>, cudaFuncAttributeMaxDynamicSharedMemorySize, GSMEM_BYTES);
    cudaFuncSetAttribute(gemm_small, cudaFuncAttributeMaxDynamicSharedMemorySize, GSMEM_BYTES);
    cudaFuncSetAttribute(context_mma_kernel, cudaFuncAttributeMaxDynamicSharedMemorySize, CTX_SMEM);

    // 0. prep (weight cvt + rowsum zero, one launch)
    prep_kernel<<<(1536 * 384 + 255) / 256, 256>>>(w_qkv, p_wq, 1536 * 384,
                                                   p_rowsum, Bb * 512);

    // 1. LN -> bf16 x_norm
    ln_norm_kernel<<<dim3(Nn_ / 32, Bb), 256>>>(x, gam, bet, p_xn);

    // 2. kv = W_kv @ xn (M=1024, one launch); k rows exp'd + rowsum atomics
    gemm_w64<0><<<dim3(8, 64, Bb), 128, GSMEM_BYTES>>>(
        p_wq + (long)512 * Dd, p_xn, p_kv, Dd, Nn_,
        0L, (long)Dd * Nn_, (long)1024 * Nn_,
        nullptr, nullptr, 0L, p_rowsum);

    // 3. partial contexts (NSPLIT=8, cp.async 3-stage)
    context_mma_kernel<<<dim3(NSPLIT, 128), 256, CTX_SMEM>>>(p_kv, p_ctxp);

    // 4. T
    build_T_kernel<<<128, 256>>>(p_ctxp, p_rowsum, w_out, p_T);

    // 5. W_final[b] = SCALE * T[b] @ W_q
    gemm_small<<<dim3(3, 3, Bb), 256, GSMEM_BYTES>>>(
        p_T, p_wq, p_wf, 512, 384,
        (long)384 * 512, 0L, (long)384 * 384, SCALE);

    // 6. out = W_final[b] @ xn + b_out + x
    gemm_w64<1><<<dim3(3, 64, Bb), 128, GSMEM_BYTES>>>(
        p_wf, p_xn, out, Dd, Nn_,
        (long)384 * 384, (long)Dd * Nn_, (long)Dd * Nn_,
        b_out, x, (long)Dd * Nn_, nullptr);
}